// round 9
// baseline (speedup 1.0000x reference)
#include <cuda_runtime.h>
#include <cuda_bf16.h>
#include <cstdint>

// ---------------- Problem constants ----------------
#define NCTX   65536
#define BATCH  2048
#define LMAX   48

// ---------------- low-level helpers ----------------
__device__ __forceinline__ uint32_t smem_u32(const void* p) {
    uint32_t a;
    asm("{ .reg .u64 t; cvta.to.shared.u64 t, %1; cvt.u32.u64 %0, t; }" : "=r"(a) : "l"(p));
    return a;
}
__device__ __forceinline__ void cp16(uint32_t s, const void* g) {
    asm volatile("cp.async.cg.shared.global [%0], [%1], 16;" :: "r"(s), "l"(g));
}
__device__ __forceinline__ void cp_commit() {
    asm volatile("cp.async.commit_group;" ::: "memory");
}
__device__ __forceinline__ void cp_wait2() {
    asm volatile("cp.async.wait_group 2;" ::: "memory");
}
__device__ __forceinline__ void ldsm4(uint32_t& r0, uint32_t& r1, uint32_t& r2, uint32_t& r3,
                                      uint32_t addr) {
    asm volatile("ldmatrix.sync.aligned.m8n8.x4.shared.b16 {%0,%1,%2,%3}, [%4];"
                 : "=r"(r0), "=r"(r1), "=r"(r2), "=r"(r3) : "r"(addr));
}
__device__ __forceinline__ void mma16816(float* c, uint32_t a0, uint32_t a1, uint32_t a2,
                                         uint32_t a3, uint32_t b0, uint32_t b1) {
    asm volatile(
        "mma.sync.aligned.m16n8k16.row.col.f32.bf16.bf16.f32 "
        "{%0,%1,%2,%3}, {%4,%5,%6,%7}, {%8,%9}, {%0,%1,%2,%3};"
        : "+f"(c[0]), "+f"(c[1]), "+f"(c[2]), "+f"(c[3])
        : "r"(a0), "r"(a1), "r"(a2), "r"(a3), "r"(b0), "r"(b1));
}
__device__ __forceinline__ void hilo_split(float v, __nv_bfloat16& h, __nv_bfloat16& l) {
    h = __float2bfloat16_rn(v);
    l = __float2bfloat16_rn(v - __bfloat162float(h));
}

// ---------------- Scratch (static device globals) ----------------
__device__ __nv_bfloat16 g_cat0h[NCTX * 2048], g_cat0l[NCTX * 2048];
__device__ __nv_bfloat16 g_a1h[NCTX * 512],  g_a1l[NCTX * 512];
__device__ __nv_bfloat16 g_a2h[NCTX * 512],  g_a2l[NCTX * 512];
__device__ __nv_bfloat16 g_dcath[BATCH * 1536], g_dcatl[BATCH * 1536];
__device__ __nv_bfloat16 g_d1h[BATCH * 512], g_d1l[BATCH * 512];
__device__ __nv_bfloat16 g_segh[BATCH * 512], g_segl[BATCH * 512];
// transposed hi/lo weights: Wt[n][k]
__device__ __nv_bfloat16 g_w1th[512 * 2048], g_w1tl[512 * 2048];
__device__ __nv_bfloat16 g_w2th[512 * 512],  g_w2tl[512 * 512];
__device__ __nv_bfloat16 g_wcth[1536 * 512], g_wctl[1536 * 512];   // composed pe_w3@Wqkv, transposed
__device__ __nv_bfloat16 g_wmth[512 * 512],  g_wmtl[512 * 512];
__device__ __nv_bfloat16 g_wlvth[512 * 512], g_wlvtl[512 * 512];
__device__ __nv_bfloat16 g_dw1th[512 * 1536], g_dw1tl[512 * 1536];
__device__ __nv_bfloat16 g_dw2th[512 * 512],  g_dw2tl[512 * 512];
__device__ float g_bc[1536];         // composed qkv bias
// fp32 buffers
__device__ float g_qkv[NCTX * 1536];
__device__ float g_seg[BATCH * 512];
__device__ float g_d2[BATCH * 512];

// ---------------- HMMA GEMM ----------------
// C[M, N] = act(A @ Wt^T + bias); CTA tile 128x256; 256 threads (8 warps, 64x64/warp).
// A: hi/lo bf16 [M,K]; Wt: hi/lo bf16 [N,K]. 3-pass split hi*hi + hi*lo + lo*hi, fp32 accum.
// BK=32, 3-stage cp.async pipeline, pass-major MMA emission (32-deep independent chains).
// ACT: 0=none 1=lrelu 2=clip. OUTF32: 1 -> fp32 outF, 0 -> hi/lo bf16.
// smem per stage: Ahi 10240 | Alo 10240 | Bhi 20480 | Blo 20480 = 61440; 3 stages = 184320
#define STG_BYTES 61440u
#define GEMM_DSM  (3 * 61440)

template <int ACT, int OUTF32>
__global__ void __launch_bounds__(256, 1)
gemm_mma(const __nv_bfloat16* __restrict__ Ahi, const __nv_bfloat16* __restrict__ Alo, int K,
         const __nv_bfloat16* __restrict__ Bhi, const __nv_bfloat16* __restrict__ Blo,
         const float* __restrict__ bias, int ldc,
         float* __restrict__ outF, __nv_bfloat16* __restrict__ outHi, __nv_bfloat16* __restrict__ outLo)
{
    extern __shared__ char dsm[];
    const uint32_t smBase = smem_u32(dsm);

    const int tid = threadIdx.x;
    const int lane = tid & 31;
    const int w = tid >> 5;          // 0..7
    const int warp_m = w >> 2;       // 0..1 (64-row slice)
    const int warp_n = w & 3;        // 0..3 (64-col slice)
    const int m0 = blockIdx.y * 128;
    const int n0 = blockIdx.x * 256;

    float c[4][8][4];                // 4 m16 x 8 n8 x 4
#pragma unroll
    for (int mi = 0; mi < 4; mi++)
#pragma unroll
        for (int ni = 0; ni < 8; ni++)
#pragma unroll
            for (int r = 0; r < 4; r++) c[mi][ni][r] = 0.f;

    const int nk = K >> 5;

    auto load_stage = [&](int s) {
        const uint32_t sb = smBase + (uint32_t)(s % 3) * STG_BYTES;
        const int k0 = s << 5;
        // A: 128 rows x 4 chunks, hi+lo
#pragma unroll
        for (int j = 0; j < 2; j++) {
            int slot = tid + j * 256;            // 0..511
            int row = slot >> 2, k8 = slot & 3;
            uint32_t dst = sb + (uint32_t)row * 80u + (uint32_t)k8 * 16u;
            size_t g = (size_t)(m0 + row) * K + k0 + k8 * 8;
            cp16(dst, Ahi + g);
            cp16(dst + 10240u, Alo + g);
        }
        // B: 256 rows x 4 chunks, hi+lo
#pragma unroll
        for (int j = 0; j < 4; j++) {
            int slot = tid + j * 256;            // 0..1023
            int row = slot >> 2, k8 = slot & 3;
            uint32_t dst = sb + 20480u + (uint32_t)row * 80u + (uint32_t)k8 * 16u;
            size_t g = (size_t)(n0 + row) * K + k0 + k8 * 8;
            cp16(dst, Bhi + g);
            cp16(dst + 20480u, Blo + g);
        }
    };

    load_stage(0); cp_commit();
    load_stage(1); cp_commit();

    const int lr = lane & 15;
    const uint32_t lc16 = (uint32_t)(lane >> 4) * 16u;

    for (int s = 0; s < nk; s++) {
        if (s + 2 < nk) load_stage(s + 2);
        cp_commit();
        cp_wait2();
        __syncthreads();

        const uint32_t sb = smBase + (uint32_t)(s % 3) * STG_BYTES;
#pragma unroll
        for (int h = 0; h < 2; h++) {
            const uint32_t koff = (uint32_t)h * 32u + lc16;
            uint32_t ah[4][4], al[4][4], bh[4][4], bl[4][4];
#pragma unroll
            for (int mi = 0; mi < 4; mi++) {
                uint32_t addr = sb + (uint32_t)((warp_m * 64 + mi * 16 + lr) * 80) + koff;
                ldsm4(ah[mi][0], ah[mi][1], ah[mi][2], ah[mi][3], addr);
                ldsm4(al[mi][0], al[mi][1], al[mi][2], al[mi][3], addr + 10240u);
            }
#pragma unroll
            for (int bt = 0; bt < 4; bt++) {
                uint32_t addr = sb + 20480u + (uint32_t)((warp_n * 64 + bt * 16 + lr) * 80) + koff;
                ldsm4(bh[bt][0], bh[bt][1], bh[bt][2], bh[bt][3], addr);
                ldsm4(bl[bt][0], bl[bt][1], bl[bt][2], bl[bt][3], addr + 20480u);
            }
            // pass-major emission: 32 independent HMMAs between accumulator reuse
#pragma unroll
            for (int ni = 0; ni < 8; ni++) {          // pass hi*hi
                const int bt = ni >> 1, sl = ni & 1;
#pragma unroll
                for (int mi = 0; mi < 4; mi++)
                    mma16816(c[mi][ni], ah[mi][0], ah[mi][1], ah[mi][2], ah[mi][3],
                             bh[bt][sl], bh[bt][sl + 2]);
            }
#pragma unroll
            for (int ni = 0; ni < 8; ni++) {          // pass hi*lo
                const int bt = ni >> 1, sl = ni & 1;
#pragma unroll
                for (int mi = 0; mi < 4; mi++)
                    mma16816(c[mi][ni], ah[mi][0], ah[mi][1], ah[mi][2], ah[mi][3],
                             bl[bt][sl], bl[bt][sl + 2]);
            }
#pragma unroll
            for (int ni = 0; ni < 8; ni++) {          // pass lo*hi
                const int bt = ni >> 1, sl = ni & 1;
#pragma unroll
                for (int mi = 0; mi < 4; mi++)
                    mma16816(c[mi][ni], al[mi][0], al[mi][1], al[mi][2], al[mi][3],
                             bh[bt][sl], bh[bt][sl + 2]);
            }
        }
        __syncthreads();
    }

    // ---- epilogue ----
#pragma unroll
    for (int mi = 0; mi < 4; mi++) {
        const int row = m0 + warp_m * 64 + mi * 16 + (lane >> 2);
#pragma unroll
        for (int ni = 0; ni < 8; ni++) {
            const int col = n0 + warp_n * 64 + ni * 8 + (lane & 3) * 2;
            const float b0 = bias[col], b1 = bias[col + 1];
            float v0 = c[mi][ni][0] + b0, v1 = c[mi][ni][1] + b1;
            float v2 = c[mi][ni][2] + b0, v3 = c[mi][ni][3] + b1;
            if (ACT == 1) {
                v0 = v0 > 0.f ? v0 : 0.2f * v0;
                v1 = v1 > 0.f ? v1 : 0.2f * v1;
                v2 = v2 > 0.f ? v2 : 0.2f * v2;
                v3 = v3 > 0.f ? v3 : 0.2f * v3;
            } else if (ACT == 2) {
                v0 = fminf(fmaxf(v0, -1.f), 1.f);
                v1 = fminf(fmaxf(v1, -1.f), 1.f);
                v2 = fminf(fmaxf(v2, -1.f), 1.f);
                v3 = fminf(fmaxf(v3, -1.f), 1.f);
            }
            if (OUTF32) {
                *(float2*)(outF + (size_t)row * ldc + col)       = make_float2(v0, v1);
                *(float2*)(outF + (size_t)(row + 8) * ldc + col) = make_float2(v2, v3);
            } else {
                __nv_bfloat16 h0, l0, h1, l1, h2, l2, h3, l3;
                hilo_split(v0, h0, l0); hilo_split(v1, h1, l1);
                hilo_split(v2, h2, l2); hilo_split(v3, h3, l3);
                *(__nv_bfloat162*)(outHi + (size_t)row * ldc + col)       = __nv_bfloat162(h0, h1);
                *(__nv_bfloat162*)(outLo + (size_t)row * ldc + col)       = __nv_bfloat162(l0, l1);
                *(__nv_bfloat162*)(outHi + (size_t)(row + 8) * ldc + col) = __nv_bfloat162(h2, h3);
                *(__nv_bfloat162*)(outLo + (size_t)(row + 8) * ldc + col) = __nv_bfloat162(l2, l3);
            }
        }
    }
}

// ---------------- fp32 -> hi/lo bf16 (strided into concat buffer) ----------------
__global__ void __launch_bounds__(256)
conv_hilo(const float* __restrict__ src, int total4, int kshift, int kmask,
          int dstStride, int dstOff,
          __nv_bfloat16* __restrict__ h, __nv_bfloat16* __restrict__ l)
{
    int i = blockIdx.x * 256 + threadIdx.x;
    if (i >= total4) return;
    int e = i << 2;
    int row = e >> kshift, col = e & kmask;
    float4 v = *(const float4*)(src + e);
    size_t o = (size_t)row * dstStride + dstOff + col;
    __nv_bfloat16 h0, l0, h1, l1, h2, l2, h3, l3;
    hilo_split(v.x, h0, l0); hilo_split(v.y, h1, l1);
    hilo_split(v.z, h2, l2); hilo_split(v.w, h3, l3);
    __nv_bfloat162* hp = (__nv_bfloat162*)(h + o);
    __nv_bfloat162* lp = (__nv_bfloat162*)(l + o);
    hp[0] = __nv_bfloat162(h0, h1); hp[1] = __nv_bfloat162(h2, h3);
    lp[0] = __nv_bfloat162(l0, l1); lp[1] = __nv_bfloat162(l2, l3);
}

// ---------------- weight transpose + hi/lo: W[K,512] -> Wt[512,K] ----------------
__global__ void __launch_bounds__(256)
wt_conv(const float* __restrict__ W, int K,
        __nv_bfloat16* __restrict__ Th, __nv_bfloat16* __restrict__ Tl)
{
    __shared__ float t[32][33];
    const int nb = blockIdx.x * 32, kb = blockIdx.y * 32;
    const int tx = threadIdx.x & 31, ty = threadIdx.x >> 5;  // 32 x 8
#pragma unroll
    for (int i = 0; i < 32; i += 8)
        t[ty + i][tx] = W[(size_t)(kb + ty + i) * 512 + nb + tx];
    __syncthreads();
#pragma unroll
    for (int i = 0; i < 32; i += 8) {
        float v = t[tx][ty + i];
        __nv_bfloat16 h, l;
        hilo_split(v, h, l);
        size_t o = (size_t)(nb + ty + i) * K + kb + tx;
        Th[o] = h; Tl[o] = l;
    }
}

// ---------------- weight composition: C = A(512x512) @ B(512x512), write Th/Tl[n*512+i] ----------------
__global__ void __launch_bounds__(256)
compose_w(const float* __restrict__ A, const float* __restrict__ B,
          __nv_bfloat16* __restrict__ Th, __nv_bfloat16* __restrict__ Tl)
{
    __shared__ float As[64][17];
    __shared__ float Bs[16][68];
    const int i0 = blockIdx.y * 64, nb0 = blockIdx.x * 64;
    const int tx = threadIdx.x & 15, ty = threadIdx.x >> 4;   // 16 x 16
    float acc[4][4] = {};
    for (int j0 = 0; j0 < 512; j0 += 16) {
        for (int t = threadIdx.x; t < 1024; t += 256) {
            int r = t >> 4, jj = t & 15;
            As[r][jj] = A[(size_t)(i0 + r) * 512 + j0 + jj];
        }
        for (int t = threadIdx.x; t < 1024; t += 256) {
            int r = t >> 6, nn = t & 63;
            Bs[r][nn] = B[(size_t)(j0 + r) * 512 + nb0 + nn];
        }
        __syncthreads();
#pragma unroll
        for (int jj = 0; jj < 16; jj++) {
            float a[4], b[4];
#pragma unroll
            for (int u = 0; u < 4; u++) a[u] = As[ty * 4 + u][jj];
#pragma unroll
            for (int u = 0; u < 4; u++) b[u] = Bs[jj][tx * 4 + u];
#pragma unroll
            for (int u = 0; u < 4; u++)
#pragma unroll
                for (int v = 0; v < 4; v++) acc[u][v] += a[u] * b[v];
        }
        __syncthreads();
    }
#pragma unroll
    for (int u = 0; u < 4; u++)
#pragma unroll
        for (int v = 0; v < 4; v++) {
            int i = i0 + ty * 4 + u, n = nb0 + tx * 4 + v;
            __nv_bfloat16 h, l;
            hilo_split(acc[u][v], h, l);
            size_t o = (size_t)n * 512 + i;
            Th[o] = h; Tl[o] = l;
        }
}

// ---------------- composed qkv bias: bc[seg*512+n] = b3 . B[:,n] + b[n] ----------------
__global__ void __launch_bounds__(512)
compose_bias(const float* __restrict__ b3,
             const float* __restrict__ Bq, const float* __restrict__ Bk, const float* __restrict__ Bv,
             const float* __restrict__ bq, const float* __restrict__ bk, const float* __restrict__ bv,
             float* __restrict__ bc)
{
    const int seg = blockIdx.x, n = threadIdx.x;
    const float* B = seg == 0 ? Bq : seg == 1 ? Bk : Bv;
    const float* bb = seg == 0 ? bq : seg == 1 ? bk : bv;
    float s = bb[n];
    for (int j = 0; j < 512; j++) s += b3[j] * B[(size_t)j * 512 + n];
    bc[seg * 512 + n] = s;
}

// ---------------- Attention per segment (reads packed qkv, stride 1536) ----------------
__global__ void __launch_bounds__(256)
attn_kernel(const float* __restrict__ qkv, const int* __restrict__ sse,
            float* __restrict__ seg_out)
{
    extern __shared__ float sm[];
    float* qs = sm;
    float* ks = sm + LMAX * 512;
    __shared__ float scores[LMAX][LMAX];
    __shared__ float colsum[LMAX];

    const int b = blockIdx.x;
    const int tid = threadIdx.x;
    const int start = sse[2 * b];
    const int end = sse[2 * b + 1];
    const int len = end - start;

    {
        const float4* g = (const float4*)(qkv + (size_t)start * 1536);
        float4* q4 = (float4*)qs;
        float4* k4 = (float4*)ks;
        int tot = len * 128;
        for (int i = tid; i < tot; i += 256) {
            int row = i >> 7, cc = i & 127;
            q4[i] = g[row * 384 + cc];
            k4[i] = g[row * 384 + 128 + cc];
        }
    }
    __syncthreads();

    {
        const int warp = tid >> 5, lane = tid & 31;
        const float scale = 0.044194173824159216f;
        const float4* q4 = (const float4*)qs;
        const float4* k4 = (const float4*)ks;
        for (int p = warp; p < len * len; p += 8) {
            int l = p / len, m = p - l * len;
            const float4* qr = q4 + l * 128 + lane;
            const float4* kr = k4 + m * 128 + lane;
            float s = 0.f;
#pragma unroll
            for (int i = 0; i < 4; i++) {
                float4 a = qr[i * 32], cc2 = kr[i * 32];
                s += a.x * cc2.x + a.y * cc2.y + a.z * cc2.z + a.w * cc2.w;
            }
#pragma unroll
            for (int off = 16; off > 0; off >>= 1)
                s += __shfl_xor_sync(0xffffffffu, s, off);
            if (lane == 0) scores[l][m] = s * scale;
        }
    }
    __syncthreads();

    if (tid < len) {
        float mx = -1e30f;
        for (int m = 0; m < len; m++) mx = fmaxf(mx, scores[tid][m]);
        float sum = 0.f;
        for (int m = 0; m < len; m++) {
            float e = __expf(scores[tid][m] - mx);
            scores[tid][m] = e; sum += e;
        }
        float inv = 1.f / sum;
        for (int m = 0; m < len; m++) scores[tid][m] *= inv;
    }
    __syncthreads();

    if (tid < len) {
        float cs = 0.f;
        for (int l = 0; l < len; l++) cs += scores[l][tid];
        colsum[tid] = cs;
    }
    __syncthreads();

    const float invlen = 1.f / (float)len;
    for (int d = tid; d < 512; d += 256) {
        float s = 0.f;
        for (int m = 0; m < len; m++)
            s += colsum[m] * qkv[(size_t)(start + m) * 1536 + 1024 + d];
        seg_out[(size_t)b * 512 + d] = s * invlen;
    }
}

// ---------------- z = normalize(mean + exp(0.5*lv)*eps) * sqrt(512) ----------------
__global__ void __launch_bounds__(256)
z_kernel(const float* __restrict__ mean, const float* __restrict__ lv,
         const float* __restrict__ eps, float* __restrict__ zout)
{
    __shared__ float red[256];
    const int b = blockIdx.x, tid = threadIdx.x;
    float zi[2];
    float ss = 0.f;
#pragma unroll
    for (int j = 0; j < 2; j++) {
        int d = tid + 256 * j;
        size_t idx = (size_t)b * 512 + d;
        float z = mean[idx] + __expf(0.5f * lv[idx]) * eps[idx];
        zi[j] = z; ss += z * z;
    }
    red[tid] = ss;
    __syncthreads();
    for (int s = 128; s > 0; s >>= 1) {
        if (tid < s) red[tid] += red[tid + s];
        __syncthreads();
    }
    float denom = fmaxf(sqrtf(red[0]), 1e-12f);
    float fac = 22.627416997969522f / denom;
#pragma unroll
    for (int j = 0; j < 2; j++) {
        int d = tid + 256 * j;
        zout[(size_t)b * 512 + d] = zi[j] * fac;
    }
}

// ---------------- final head matvec ----------------
__global__ void __launch_bounds__(256)
matvec_kernel(const float* __restrict__ A, const float* __restrict__ w,
              const float* __restrict__ b, float* __restrict__ out)
{
    const int lane = threadIdx.x;
    const int row = blockIdx.x * 8 + threadIdx.y;
    float s = 0.f;
    for (int k = lane; k < 512; k += 32)
        s += A[(size_t)row * 512 + k] * w[k];
#pragma unroll
    for (int off = 16; off > 0; off >>= 1)
        s += __shfl_xor_sync(0xffffffffu, s, off);
    if (lane == 0) out[row] = s + b[0];
}

// ---------------- host side ----------------
extern "C" void kernel_launch(void* const* d_in, const int* in_sizes, int n_in,
                              void* d_out, int out_size)
{
    const float* tc    = (const float*)d_in[0];
    const float* tr    = (const float*)d_in[1];
    const float* cc    = (const float*)d_in[2];
    const float* cr    = (const float*)d_in[3];
    const float* eps   = (const float*)d_in[4];
    const float* pe_w1 = (const float*)d_in[5];
    const float* pe_b1 = (const float*)d_in[6];
    const float* pe_w2 = (const float*)d_in[7];
    const float* pe_b2 = (const float*)d_in[8];
    const float* pe_w3 = (const float*)d_in[9];
    const float* pe_b3 = (const float*)d_in[10];
    const float* wq    = (const float*)d_in[11];
    const float* bq    = (const float*)d_in[12];
    const float* wk    = (const float*)d_in[13];
    const float* bk    = (const float*)d_in[14];
    const float* wv    = (const float*)d_in[15];
    const float* bv    = (const float*)d_in[16];
    const float* wm    = (const float*)d_in[17];
    const float* bm    = (const float*)d_in[18];
    const float* wlv   = (const float*)d_in[19];
    const float* blv   = (const float*)d_in[20];
    const float* d_w1  = (const float*)d_in[21];
    const float* d_b1  = (const float*)d_in[22];
    const float* d_w2  = (const float*)d_in[23];
    const float* d_b2  = (const float*)d_in[24];
    const float* d_w3  = (const float*)d_in[25];
    const float* d_b3  = (const float*)d_in[26];
    const int*   sse   = (const int*)d_in[27];

    float* out = (float*)d_out;
    float* out_rc   = out;
    float* out_rr   = out + BATCH;
    float* out_mean = out + 2 * BATCH;
    float* out_lv   = out_mean + BATCH * 512;
    float* out_z    = out_lv + BATCH * 512;

    __nv_bfloat16 *cat0h, *cat0l, *a1h, *a1l, *a2h, *a2l;
    __nv_bfloat16 *dcath, *dcatl, *d1h, *d1l, *segh, *segl;
    __nv_bfloat16 *w1th, *w1tl, *w2th, *w2tl, *wcth, *wctl;
    __nv_bfloat16 *wmth, *wmtl, *wlvth, *wlvtl;
    __nv_bfloat16 *dw1th, *dw1tl, *dw2th, *dw2tl;
    float *qkvf, *seg, *d2f, *bc;
    cudaGetSymbolAddress((void**)&cat0h, g_cat0h); cudaGetSymbolAddress((void**)&cat0l, g_cat0l);
    cudaGetSymbolAddress((void**)&a1h, g_a1h);     cudaGetSymbolAddress((void**)&a1l, g_a1l);
    cudaGetSymbolAddress((void**)&a2h, g_a2h);     cudaGetSymbolAddress((void**)&a2l, g_a2l);
    cudaGetSymbolAddress((void**)&dcath, g_dcath); cudaGetSymbolAddress((void**)&dcatl, g_dcatl);
    cudaGetSymbolAddress((void**)&d1h, g_d1h);     cudaGetSymbolAddress((void**)&d1l, g_d1l);
    cudaGetSymbolAddress((void**)&segh, g_segh);   cudaGetSymbolAddress((void**)&segl, g_segl);
    cudaGetSymbolAddress((void**)&w1th, g_w1th);   cudaGetSymbolAddress((void**)&w1tl, g_w1tl);
    cudaGetSymbolAddress((void**)&w2th, g_w2th);   cudaGetSymbolAddress((void**)&w2tl, g_w2tl);
    cudaGetSymbolAddress((void**)&wcth, g_wcth);   cudaGetSymbolAddress((void**)&wctl, g_wctl);
    cudaGetSymbolAddress((void**)&wmth, g_wmth);   cudaGetSymbolAddress((void**)&wmtl, g_wmtl);
    cudaGetSymbolAddress((void**)&wlvth, g_wlvth); cudaGetSymbolAddress((void**)&wlvtl, g_wlvtl);
    cudaGetSymbolAddress((void**)&dw1th, g_dw1th); cudaGetSymbolAddress((void**)&dw1tl, g_dw1tl);
    cudaGetSymbolAddress((void**)&dw2th, g_dw2th); cudaGetSymbolAddress((void**)&dw2tl, g_dw2tl);
    cudaGetSymbolAddress((void**)&qkvf, g_qkv);
    cudaGetSymbolAddress((void**)&seg, g_seg);
    cudaGetSymbolAddress((void**)&d2f, g_d2);
    cudaGetSymbolAddress((void**)&bc, g_bc);

    cudaFuncSetAttribute(gemm_mma<0, 1>, cudaFuncAttributeMaxDynamicSharedMemorySize, GEMM_DSM);
    cudaFuncSetAttribute(gemm_mma<1, 0>, cudaFuncAttributeMaxDynamicSharedMemorySize, GEMM_DSM);
    cudaFuncSetAttribute(gemm_mma<1, 1>, cudaFuncAttributeMaxDynamicSharedMemorySize, GEMM_DSM);
    cudaFuncSetAttribute(gemm_mma<2, 1>, cudaFuncAttributeMaxDynamicSharedMemorySize, GEMM_DSM);
    const int attn_smem = LMAX * 512 * 2 * (int)sizeof(float);
    cudaFuncSetAttribute(attn_kernel, cudaFuncAttributeMaxDynamicSharedMemorySize, attn_smem);

    // input conv + layer-1 weight
    conv_hilo<<<NCTX * 1024 / 4 / 256, 256>>>(cc, NCTX * 1024 / 4, 10, 1023, 2048, 0, cat0h, cat0l);
    conv_hilo<<<NCTX * 1024 / 4 / 256, 256>>>(cr, NCTX * 1024 / 4, 10, 1023, 2048, 1024, cat0h, cat0l);
    wt_conv<<<dim3(16, 64), 256>>>(pe_w1, 2048, w1th, w1tl);

    // layer 1 (K=2048)
    gemm_mma<1, 0><<<dim3(2, NCTX / 128), 256, GEMM_DSM>>>(cat0h, cat0l, 2048, w1th, w1tl, pe_b1, 512, nullptr, a1h, a1l);

    wt_conv<<<dim3(16, 16), 256>>>(pe_w2, 512, w2th, w2tl);

    // layer 2 (K=512)
    gemm_mma<1, 0><<<dim3(2, NCTX / 128), 256, GEMM_DSM>>>(a1h, a1l, 512, w2th, w2tl, pe_b2, 512, nullptr, a2h, a2l);

    // compose pe_w3 into qkv weights + bias
    compose_w<<<dim3(8, 8), 256>>>(pe_w3, wq, wcth, wctl);
    compose_w<<<dim3(8, 8), 256>>>(pe_w3, wk, wcth + (size_t)512 * 512, wctl + (size_t)512 * 512);
    compose_w<<<dim3(8, 8), 256>>>(pe_w3, wv, wcth + (size_t)1024 * 512, wctl + (size_t)1024 * 512);
    compose_bias<<<3, 512>>>(pe_b3, wq, wk, wv, bq, bk, bv, bc);

    // fused qkv projection from a2: [NCTX, 1536] fp32
    gemm_mma<0, 1><<<dim3(6, NCTX / 128), 256, GEMM_DSM>>>(a2h, a2l, 512, wcth, wctl, bc, 1536, qkvf, nullptr, nullptr);

    // attention
    attn_kernel<<<BATCH, 256, attn_smem>>>(qkvf, sse, seg);

    // heads (clip)
    wt_conv<<<dim3(16, 16), 256>>>(wm, 512, wmth, wmtl);
    wt_conv<<<dim3(16, 16), 256>>>(wlv, 512, wlvth, wlvtl);
    conv_hilo<<<BATCH * 512 / 4 / 256, 256>>>(seg, BATCH * 512 / 4, 9, 511, 512, 0, segh, segl);
    gemm_mma<2, 1><<<dim3(2, BATCH / 128), 256, GEMM_DSM>>>(segh, segl, 512, wmth, wmtl, bm, 512, out_mean, nullptr, nullptr);
    gemm_mma<2, 1><<<dim3(2, BATCH / 128), 256, GEMM_DSM>>>(segh, segl, 512, wlvth, wlvtl, blv, 512, out_lv, nullptr, nullptr);

    // z
    z_kernel<<<BATCH, 256>>>(out_mean, out_lv, eps, out_z);

    // decoder weights
    wt_conv<<<dim3(16, 48), 256>>>(d_w1, 1536, dw1th, dw1tl);
    wt_conv<<<dim3(16, 16), 256>>>(d_w2, 512, dw2th, dw2tl);

    // decoder concat z part (cols 1024..1535, shared by both passes)
    conv_hilo<<<BATCH * 512 / 4 / 256, 256>>>(out_z, BATCH * 512 / 4, 9, 511, 1536, 1024, dcath, dcatl);

    // decoder (chosen)
    conv_hilo<<<BATCH * 1024 / 4 / 256, 256>>>(tc, BATCH * 1024 / 4, 10, 1023, 1536, 0, dcath, dcatl);
    gemm_mma<1, 0><<<dim3(2, BATCH / 128), 256, GEMM_DSM>>>(dcath, dcatl, 1536, dw1th, dw1tl, d_b1, 512, nullptr, d1h, d1l);
    gemm_mma<1, 1><<<dim3(2, BATCH / 128), 256, GEMM_DSM>>>(d1h, d1l, 512, dw2th, dw2tl, d_b2, 512, d2f, nullptr, nullptr);
    matvec_kernel<<<BATCH / 8, dim3(32, 8)>>>(d2f, d_w3, d_b3, out_rc);

    // decoder (rejected)
    conv_hilo<<<BATCH * 1024 / 4 / 256, 256>>>(tr, BATCH * 1024 / 4, 10, 1023, 1536, 0, dcath, dcatl);
    gemm_mma<1, 0><<<dim3(2, BATCH / 128), 256, GEMM_DSM>>>(dcath, dcatl, 1536, dw1th, dw1tl, d_b1, 512, nullptr, d1h, d1l);
    gemm_mma<1, 1><<<dim3(2, BATCH / 128), 256, GEMM_DSM>>>(d1h, d1l, 512, dw2th, dw2tl, d_b2, 512, d2f, nullptr, nullptr);
    matvec_kernel<<<BATCH / 8, dim3(32, 8)>>>(d2f, d_w3, d_b3, out_rr);

    (void)in_sizes; (void)n_in; (void)out_size;
}

// round 11
// speedup vs baseline: 1.3635x; 1.3635x over previous
#include <cuda_runtime.h>
#include <cuda_fp16.h>
#include <cstdint>

// ---------------- Problem constants ----------------
#define NCTX   65536
#define BATCH  2048
#define LMAX   48

// ---------------- low-level helpers ----------------
__device__ __forceinline__ uint32_t smem_u32(const void* p) {
    uint32_t a;
    asm("{ .reg .u64 t; cvta.to.shared.u64 t, %1; cvt.u32.u64 %0, t; }" : "=r"(a) : "l"(p));
    return a;
}
__device__ __forceinline__ void cp16(uint32_t s, const void* g) {
    asm volatile("cp.async.cg.shared.global [%0], [%1], 16;" :: "r"(s), "l"(g));
}
__device__ __forceinline__ void cp_commit() {
    asm volatile("cp.async.commit_group;" ::: "memory");
}
__device__ __forceinline__ void cp_wait1() {
    asm volatile("cp.async.wait_group 1;" ::: "memory");
}
__device__ __forceinline__ void ldsm4(uint32_t& r0, uint32_t& r1, uint32_t& r2, uint32_t& r3,
                                      uint32_t addr) {
    asm volatile("ldmatrix.sync.aligned.m8n8.x4.shared.b16 {%0,%1,%2,%3}, [%4];"
                 : "=r"(r0), "=r"(r1), "=r"(r2), "=r"(r3) : "r"(addr));
}
__device__ __forceinline__ void mma16816(float* c, uint32_t a0, uint32_t a1, uint32_t a2,
                                         uint32_t a3, uint32_t b0, uint32_t b1) {
    asm volatile(
        "mma.sync.aligned.m16n8k16.row.col.f32.f16.f16.f32 "
        "{%0,%1,%2,%3}, {%4,%5,%6,%7}, {%8,%9}, {%0,%1,%2,%3};"
        : "+f"(c[0]), "+f"(c[1]), "+f"(c[2]), "+f"(c[3])
        : "r"(a0), "r"(a1), "r"(a2), "r"(a3), "r"(b0), "r"(b1));
}
__device__ __forceinline__ void hilo_split(float v, __half& h, __half& l) {
    h = __float2half_rn(v);
    l = __float2half_rn(v - __half2float(h));
}

// ---------------- Scratch (static device globals) ----------------
__device__ __half g_cat0h[NCTX * 2048], g_cat0l[NCTX * 2048];
__device__ __half g_a1h[NCTX * 512],  g_a1l[NCTX * 512];
__device__ __half g_a2h[NCTX * 512],  g_a2l[NCTX * 512];
__device__ __half g_dcath[BATCH * 1536], g_dcatl[BATCH * 1536];
__device__ __half g_d1h[BATCH * 512], g_d1l[BATCH * 512];
__device__ __half g_segh[BATCH * 512], g_segl[BATCH * 512];
// transposed single-fp16 weights: Wt[n][k]
__device__ __half g_w1t[512 * 2048];
__device__ __half g_w2t[512 * 512];
__device__ __half g_wct[1536 * 512];   // composed pe_w3@Wqkv, transposed
__device__ __half g_wmt[512 * 512];
__device__ __half g_wlvt[512 * 512];
__device__ __half g_dw1t[512 * 1536];
__device__ __half g_dw2t[512 * 512];
__device__ float g_bc[1536];           // composed qkv bias
// fp32 buffers
__device__ float g_qkv[NCTX * 1536];
__device__ float g_seg[BATCH * 512];
__device__ float g_d2[BATCH * 512];

// ---------------- HMMA GEMM (fp16 2-pass) ----------------
// C[M, N] = act((Ahi + Alo) @ Bt^T + bias); CTA 128x128; 8 warps, 64x32 warp tile.
// A split hi/lo fp16 (exact to ~2^-22); B single fp16 (weights). fp32 accum.
// BK=32, 3-stage cp.async pipeline (race-free order: wait->sync->load->compute), 2 CTAs/SM.
// ACT: 0=none 1=lrelu 2=clip. OUTF32: 1 -> fp32 outF, 0 -> hi/lo fp16.
// smem stage: Ahi 10240 | Alo 10240 | B 10240 = 30720; 3 stages = 92160
#define STG_BYTES 30720u
#define GEMM_DSM  (3 * 30720)

template <int ACT, int OUTF32>
__global__ void __launch_bounds__(256, 2)
gemm_mma(const __half* __restrict__ Ahi, const __half* __restrict__ Alo, int K,
         const __half* __restrict__ Bt,
         const float* __restrict__ bias, int ldc,
         float* __restrict__ outF, __half* __restrict__ outHi, __half* __restrict__ outLo)
{
    extern __shared__ char dsm[];
    const uint32_t smBase = smem_u32(dsm);

    const int tid = threadIdx.x;
    const int lane = tid & 31;
    const int w = tid >> 5;          // 0..7
    const int warp_m = w >> 2;       // 0..1 (64-row slice)
    const int warp_n = w & 3;        // 0..3 (32-col slice)
    const int m0 = blockIdx.y * 128;
    const int n0 = blockIdx.x * 128;

    float c[4][4][4];
#pragma unroll
    for (int mi = 0; mi < 4; mi++)
#pragma unroll
        for (int ni = 0; ni < 4; ni++)
#pragma unroll
            for (int r = 0; r < 4; r++) c[mi][ni][r] = 0.f;

    const int nk = K >> 5;

    // stage loader: 512 slots per matrix (128 rows x 4 16B-chunks); 6 cp16/thread
    auto load_stage = [&](int s) {
        const uint32_t sb = smBase + (uint32_t)(s % 3) * STG_BYTES;
        const int k0 = s << 5;
#pragma unroll
        for (int j = 0; j < 2; j++) {
            int slot = tid + j * 256;            // 0..511
            int row = slot >> 2, k8 = slot & 3;
            uint32_t dst = sb + (uint32_t)row * 80u + (uint32_t)k8 * 16u;
            size_t ga = (size_t)(m0 + row) * K + k0 + k8 * 8;
            size_t gb = (size_t)(n0 + row) * K + k0 + k8 * 8;
            cp16(dst,           Ahi + ga);
            cp16(dst + 10240u,  Alo + ga);
            cp16(dst + 20480u,  Bt + gb);
        }
    };

    load_stage(0); cp_commit();
    load_stage(1); cp_commit();

    const int lr = lane & 15;
    const uint32_t lc16 = (uint32_t)(lane >> 4) * 16u;

    for (int s = 0; s < nk; s++) {
        cp_wait1();                 // stage s resident (s+1 may still fly)
        __syncthreads();            // all warps done with stage s-1 -> safe to overwrite
        if (s + 2 < nk) load_stage(s + 2);
        cp_commit();

        const uint32_t sb = smBase + (uint32_t)(s % 3) * STG_BYTES;
#pragma unroll
        for (int h = 0; h < 2; h++) {
            const uint32_t koff = (uint32_t)h * 32u + lc16;
            uint32_t ah[4][4], al[4][4], bb[2][4];
#pragma unroll
            for (int mi = 0; mi < 4; mi++) {
                uint32_t addr = sb + (uint32_t)((warp_m * 64 + mi * 16 + lr) * 80) + koff;
                ldsm4(ah[mi][0], ah[mi][1], ah[mi][2], ah[mi][3], addr);
                ldsm4(al[mi][0], al[mi][1], al[mi][2], al[mi][3], addr + 10240u);
            }
#pragma unroll
            for (int bt = 0; bt < 2; bt++) {
                uint32_t addr = sb + 20480u + (uint32_t)((warp_n * 32 + bt * 16 + lr) * 80) + koff;
                ldsm4(bb[bt][0], bb[bt][1], bb[bt][2], bb[bt][3], addr);
            }
            // pass-major: 16 independent HMMAs between accumulator reuse
#pragma unroll
            for (int ni = 0; ni < 4; ni++) {          // pass hi
                const int bt = ni >> 1, sl = ni & 1;
#pragma unroll
                for (int mi = 0; mi < 4; mi++)
                    mma16816(c[mi][ni], ah[mi][0], ah[mi][1], ah[mi][2], ah[mi][3],
                             bb[bt][sl], bb[bt][sl + 2]);
            }
#pragma unroll
            for (int ni = 0; ni < 4; ni++) {          // pass lo
                const int bt = ni >> 1, sl = ni & 1;
#pragma unroll
                for (int mi = 0; mi < 4; mi++)
                    mma16816(c[mi][ni], al[mi][0], al[mi][1], al[mi][2], al[mi][3],
                             bb[bt][sl], bb[bt][sl + 2]);
            }
        }
    }

    // ---- epilogue ----
#pragma unroll
    for (int mi = 0; mi < 4; mi++) {
        const int row = m0 + warp_m * 64 + mi * 16 + (lane >> 2);
#pragma unroll
        for (int ni = 0; ni < 4; ni++) {
            const int col = n0 + warp_n * 32 + ni * 8 + (lane & 3) * 2;
            const float b0 = bias[col], b1 = bias[col + 1];
            float v0 = c[mi][ni][0] + b0, v1 = c[mi][ni][1] + b1;
            float v2 = c[mi][ni][2] + b0, v3 = c[mi][ni][3] + b1;
            if (ACT == 1) {
                v0 = v0 > 0.f ? v0 : 0.2f * v0;
                v1 = v1 > 0.f ? v1 : 0.2f * v1;
                v2 = v2 > 0.f ? v2 : 0.2f * v2;
                v3 = v3 > 0.f ? v3 : 0.2f * v3;
            } else if (ACT == 2) {
                v0 = fminf(fmaxf(v0, -1.f), 1.f);
                v1 = fminf(fmaxf(v1, -1.f), 1.f);
                v2 = fminf(fmaxf(v2, -1.f), 1.f);
                v3 = fminf(fmaxf(v3, -1.f), 1.f);
            }
            if (OUTF32) {
                *(float2*)(outF + (size_t)row * ldc + col)       = make_float2(v0, v1);
                *(float2*)(outF + (size_t)(row + 8) * ldc + col) = make_float2(v2, v3);
            } else {
                __half h0, l0, h1, l1, h2, l2, h3, l3;
                hilo_split(v0, h0, l0); hilo_split(v1, h1, l1);
                hilo_split(v2, h2, l2); hilo_split(v3, h3, l3);
                *(__half2*)(outHi + (size_t)row * ldc + col)       = __halves2half2(h0, h1);
                *(__half2*)(outLo + (size_t)row * ldc + col)       = __halves2half2(l0, l1);
                *(__half2*)(outHi + (size_t)(row + 8) * ldc + col) = __halves2half2(h2, h3);
                *(__half2*)(outLo + (size_t)(row + 8) * ldc + col) = __halves2half2(l2, l3);
            }
        }
    }
}

// ---------------- fp32 -> hi/lo fp16 (strided into concat buffer) ----------------
__global__ void __launch_bounds__(256)
conv_hilo(const float* __restrict__ src, int total4, int kshift, int kmask,
          int dstStride, int dstOff,
          __half* __restrict__ h, __half* __restrict__ l)
{
    int i = blockIdx.x * 256 + threadIdx.x;
    if (i >= total4) return;
    int e = i << 2;
    int row = e >> kshift, col = e & kmask;
    float4 v = *(const float4*)(src + e);
    size_t o = (size_t)row * dstStride + dstOff + col;
    __half h0, l0, h1, l1, h2, l2, h3, l3;
    hilo_split(v.x, h0, l0); hilo_split(v.y, h1, l1);
    hilo_split(v.z, h2, l2); hilo_split(v.w, h3, l3);
    __half2* hp = (__half2*)(h + o);
    __half2* lp = (__half2*)(l + o);
    hp[0] = __halves2half2(h0, h1); hp[1] = __halves2half2(h2, h3);
    lp[0] = __halves2half2(l0, l1); lp[1] = __halves2half2(l2, l3);
}

// ---------------- weight transpose + fp16: W[K,512] -> Wt[512,K] ----------------
__global__ void __launch_bounds__(256)
wt_conv(const float* __restrict__ W, int K, __half* __restrict__ T)
{
    __shared__ float t[32][33];
    const int nb = blockIdx.x * 32, kb = blockIdx.y * 32;
    const int tx = threadIdx.x & 31, ty = threadIdx.x >> 5;  // 32 x 8
#pragma unroll
    for (int i = 0; i < 32; i += 8)
        t[ty + i][tx] = W[(size_t)(kb + ty + i) * 512 + nb + tx];
    __syncthreads();
#pragma unroll
    for (int i = 0; i < 32; i += 8)
        T[(size_t)(nb + ty + i) * K + kb + tx] = __float2half_rn(t[tx][ty + i]);
}

// ---------------- weight composition: C = A(512x512)@B(512x512) -> T[n*512+i] fp16 ----------------
__global__ void __launch_bounds__(256)
compose_w(const float* __restrict__ A, const float* __restrict__ B, __half* __restrict__ T)
{
    __shared__ float As[64][17];
    __shared__ float Bs[16][68];
    const int i0 = blockIdx.y * 64, nb0 = blockIdx.x * 64;
    const int tx = threadIdx.x & 15, ty = threadIdx.x >> 4;   // 16 x 16
    float acc[4][4] = {};
    for (int j0 = 0; j0 < 512; j0 += 16) {
        for (int t = threadIdx.x; t < 1024; t += 256) {
            int r = t >> 4, jj = t & 15;
            As[r][jj] = A[(size_t)(i0 + r) * 512 + j0 + jj];
        }
        for (int t = threadIdx.x; t < 1024; t += 256) {
            int r = t >> 6, nn = t & 63;
            Bs[r][nn] = B[(size_t)(j0 + r) * 512 + nb0 + nn];
        }
        __syncthreads();
#pragma unroll
        for (int jj = 0; jj < 16; jj++) {
            float a[4], b[4];
#pragma unroll
            for (int u = 0; u < 4; u++) a[u] = As[ty * 4 + u][jj];
#pragma unroll
            for (int u = 0; u < 4; u++) b[u] = Bs[jj][tx * 4 + u];
#pragma unroll
            for (int u = 0; u < 4; u++)
#pragma unroll
                for (int v = 0; v < 4; v++) acc[u][v] += a[u] * b[v];
        }
        __syncthreads();
    }
#pragma unroll
    for (int u = 0; u < 4; u++)
#pragma unroll
        for (int v = 0; v < 4; v++) {
            int i = i0 + ty * 4 + u, n = nb0 + tx * 4 + v;
            T[(size_t)n * 512 + i] = __float2half_rn(acc[u][v]);
        }
}

// ---------------- composed qkv bias: bc[seg*512+n] = b3 . B[:,n] + b[n] ----------------
__global__ void __launch_bounds__(512)
compose_bias(const float* __restrict__ b3,
             const float* __restrict__ Bq, const float* __restrict__ Bk, const float* __restrict__ Bv,
             const float* __restrict__ bq, const float* __restrict__ bk, const float* __restrict__ bv,
             float* __restrict__ bc)
{
    const int seg = blockIdx.x, n = threadIdx.x;
    const float* B = seg == 0 ? Bq : seg == 1 ? Bk : Bv;
    const float* bb = seg == 0 ? bq : seg == 1 ? bk : bv;
    float s = bb[n];
    for (int j = 0; j < 512; j++) s += b3[j] * B[(size_t)j * 512 + n];
    bc[seg * 512 + n] = s;
}

// ---------------- Attention per segment (reads packed qkv, stride 1536) ----------------
__global__ void __launch_bounds__(256)
attn_kernel(const float* __restrict__ qkv, const int* __restrict__ sse,
            float* __restrict__ seg_out)
{
    extern __shared__ float sm[];
    float* qs = sm;
    float* ks = sm + LMAX * 512;
    __shared__ float scores[LMAX][LMAX];
    __shared__ float colsum[LMAX];

    const int b = blockIdx.x;
    const int tid = threadIdx.x;
    const int start = sse[2 * b];
    const int end = sse[2 * b + 1];
    const int len = end - start;

    {
        const float4* g = (const float4*)(qkv + (size_t)start * 1536);
        float4* q4 = (float4*)qs;
        float4* k4 = (float4*)ks;
        int tot = len * 128;
        for (int i = tid; i < tot; i += 256) {
            int row = i >> 7, cc = i & 127;
            q4[i] = g[row * 384 + cc];
            k4[i] = g[row * 384 + 128 + cc];
        }
    }
    __syncthreads();

    {
        const int warp = tid >> 5, lane = tid & 31;
        const float scale = 0.044194173824159216f;
        const float4* q4 = (const float4*)qs;
        const float4* k4 = (const float4*)ks;
        for (int p = warp; p < len * len; p += 8) {
            int l = p / len, m = p - l * len;
            const float4* qr = q4 + l * 128 + lane;
            const float4* kr = k4 + m * 128 + lane;
            float s = 0.f;
#pragma unroll
            for (int i = 0; i < 4; i++) {
                float4 a = qr[i * 32], cc2 = kr[i * 32];
                s += a.x * cc2.x + a.y * cc2.y + a.z * cc2.z + a.w * cc2.w;
            }
#pragma unroll
            for (int off = 16; off > 0; off >>= 1)
                s += __shfl_xor_sync(0xffffffffu, s, off);
            if (lane == 0) scores[l][m] = s * scale;
        }
    }
    __syncthreads();

    if (tid < len) {
        float mx = -1e30f;
        for (int m = 0; m < len; m++) mx = fmaxf(mx, scores[tid][m]);
        float sum = 0.f;
        for (int m = 0; m < len; m++) {
            float e = __expf(scores[tid][m] - mx);
            scores[tid][m] = e; sum += e;
        }
        float inv = 1.f / sum;
        for (int m = 0; m < len; m++) scores[tid][m] *= inv;
    }
    __syncthreads();

    if (tid < len) {
        float cs = 0.f;
        for (int l = 0; l < len; l++) cs += scores[l][tid];
        colsum[tid] = cs;
    }
    __syncthreads();

    const float invlen = 1.f / (float)len;
    for (int d = tid; d < 512; d += 256) {
        float s = 0.f;
        for (int m = 0; m < len; m++)
            s += colsum[m] * qkv[(size_t)(start + m) * 1536 + 1024 + d];
        seg_out[(size_t)b * 512 + d] = s * invlen;
    }
}

// ---------------- z = normalize(mean + exp(0.5*lv)*eps) * sqrt(512) ----------------
__global__ void __launch_bounds__(256)
z_kernel(const float* __restrict__ mean, const float* __restrict__ lv,
         const float* __restrict__ eps, float* __restrict__ zout)
{
    __shared__ float red[256];
    const int b = blockIdx.x, tid = threadIdx.x;
    float zi[2];
    float ss = 0.f;
#pragma unroll
    for (int j = 0; j < 2; j++) {
        int d = tid + 256 * j;
        size_t idx = (size_t)b * 512 + d;
        float z = mean[idx] + __expf(0.5f * lv[idx]) * eps[idx];
        zi[j] = z; ss += z * z;
    }
    red[tid] = ss;
    __syncthreads();
    for (int s = 128; s > 0; s >>= 1) {
        if (tid < s) red[tid] += red[tid + s];
        __syncthreads();
    }
    float denom = fmaxf(sqrtf(red[0]), 1e-12f);
    float fac = 22.627416997969522f / denom;
#pragma unroll
    for (int j = 0; j < 2; j++) {
        int d = tid + 256 * j;
        zout[(size_t)b * 512 + d] = zi[j] * fac;
    }
}

// ---------------- final head matvec ----------------
__global__ void __launch_bounds__(256)
matvec_kernel(const float* __restrict__ A, const float* __restrict__ w,
              const float* __restrict__ b, float* __restrict__ out)
{
    const int lane = threadIdx.x;
    const int row = blockIdx.x * 8 + threadIdx.y;
    float s = 0.f;
    for (int k = lane; k < 512; k += 32)
        s += A[(size_t)row * 512 + k] * w[k];
#pragma unroll
    for (int off = 16; off > 0; off >>= 1)
        s += __shfl_xor_sync(0xffffffffu, s, off);
    if (lane == 0) out[row] = s + b[0];
}

// ---------------- host side ----------------
extern "C" void kernel_launch(void* const* d_in, const int* in_sizes, int n_in,
                              void* d_out, int out_size)
{
    const float* tc    = (const float*)d_in[0];
    const float* tr    = (const float*)d_in[1];
    const float* cc    = (const float*)d_in[2];
    const float* cr    = (const float*)d_in[3];
    const float* eps   = (const float*)d_in[4];
    const float* pe_w1 = (const float*)d_in[5];
    const float* pe_b1 = (const float*)d_in[6];
    const float* pe_w2 = (const float*)d_in[7];
    const float* pe_b2 = (const float*)d_in[8];
    const float* pe_w3 = (const float*)d_in[9];
    const float* pe_b3 = (const float*)d_in[10];
    const float* wq    = (const float*)d_in[11];
    const float* bq    = (const float*)d_in[12];
    const float* wk    = (const float*)d_in[13];
    const float* bk    = (const float*)d_in[14];
    const float* wv    = (const float*)d_in[15];
    const float* bv    = (const float*)d_in[16];
    const float* wm    = (const float*)d_in[17];
    const float* bm    = (const float*)d_in[18];
    const float* wlv   = (const float*)d_in[19];
    const float* blv   = (const float*)d_in[20];
    const float* d_w1  = (const float*)d_in[21];
    const float* d_b1  = (const float*)d_in[22];
    const float* d_w2  = (const float*)d_in[23];
    const float* d_b2  = (const float*)d_in[24];
    const float* d_w3  = (const float*)d_in[25];
    const float* d_b3  = (const float*)d_in[26];
    const int*   sse   = (const int*)d_in[27];

    float* out = (float*)d_out;
    float* out_rc   = out;
    float* out_rr   = out + BATCH;
    float* out_mean = out + 2 * BATCH;
    float* out_lv   = out_mean + BATCH * 512;
    float* out_z    = out_lv + BATCH * 512;

    __half *cat0h, *cat0l, *a1h, *a1l, *a2h, *a2l;
    __half *dcath, *dcatl, *d1h, *d1l, *segh, *segl;
    __half *w1t, *w2t, *wct, *wmt, *wlvt, *dw1t, *dw2t;
    float *qkvf, *seg, *d2f, *bc;
    cudaGetSymbolAddress((void**)&cat0h, g_cat0h); cudaGetSymbolAddress((void**)&cat0l, g_cat0l);
    cudaGetSymbolAddress((void**)&a1h, g_a1h);     cudaGetSymbolAddress((void**)&a1l, g_a1l);
    cudaGetSymbolAddress((void**)&a2h, g_a2h);     cudaGetSymbolAddress((void**)&a2l, g_a2l);
    cudaGetSymbolAddress((void**)&dcath, g_dcath); cudaGetSymbolAddress((void**)&dcatl, g_dcatl);
    cudaGetSymbolAddress((void**)&d1h, g_d1h);     cudaGetSymbolAddress((void**)&d1l, g_d1l);
    cudaGetSymbolAddress((void**)&segh, g_segh);   cudaGetSymbolAddress((void**)&segl, g_segl);
    cudaGetSymbolAddress((void**)&w1t, g_w1t);
    cudaGetSymbolAddress((void**)&w2t, g_w2t);
    cudaGetSymbolAddress((void**)&wct, g_wct);
    cudaGetSymbolAddress((void**)&wmt, g_wmt);
    cudaGetSymbolAddress((void**)&wlvt, g_wlvt);
    cudaGetSymbolAddress((void**)&dw1t, g_dw1t);
    cudaGetSymbolAddress((void**)&dw2t, g_dw2t);
    cudaGetSymbolAddress((void**)&qkvf, g_qkv);
    cudaGetSymbolAddress((void**)&seg, g_seg);
    cudaGetSymbolAddress((void**)&d2f, g_d2);
    cudaGetSymbolAddress((void**)&bc, g_bc);

    cudaFuncSetAttribute(gemm_mma<0, 1>, cudaFuncAttributeMaxDynamicSharedMemorySize, GEMM_DSM);
    cudaFuncSetAttribute(gemm_mma<1, 0>, cudaFuncAttributeMaxDynamicSharedMemorySize, GEMM_DSM);
    cudaFuncSetAttribute(gemm_mma<1, 1>, cudaFuncAttributeMaxDynamicSharedMemorySize, GEMM_DSM);
    cudaFuncSetAttribute(gemm_mma<2, 1>, cudaFuncAttributeMaxDynamicSharedMemorySize, GEMM_DSM);
    const int attn_smem = LMAX * 512 * 2 * (int)sizeof(float);
    cudaFuncSetAttribute(attn_kernel, cudaFuncAttributeMaxDynamicSharedMemorySize, attn_smem);

    // input conv + layer-1 weight
    conv_hilo<<<NCTX * 1024 / 4 / 256, 256>>>(cc, NCTX * 1024 / 4, 10, 1023, 2048, 0, cat0h, cat0l);
    conv_hilo<<<NCTX * 1024 / 4 / 256, 256>>>(cr, NCTX * 1024 / 4, 10, 1023, 2048, 1024, cat0h, cat0l);
    wt_conv<<<dim3(16, 64), 256>>>(pe_w1, 2048, w1t);

    // layer 1 (K=2048)
    gemm_mma<1, 0><<<dim3(4, NCTX / 128), 256, GEMM_DSM>>>(cat0h, cat0l, 2048, w1t, pe_b1, 512, nullptr, a1h, a1l);

    wt_conv<<<dim3(16, 16), 256>>>(pe_w2, 512, w2t);

    // layer 2 (K=512)
    gemm_mma<1, 0><<<dim3(4, NCTX / 128), 256, GEMM_DSM>>>(a1h, a1l, 512, w2t, pe_b2, 512, nullptr, a2h, a2l);

    // compose pe_w3 into qkv weights + bias
    compose_w<<<dim3(8, 8), 256>>>(pe_w3, wq, wct);
    compose_w<<<dim3(8, 8), 256>>>(pe_w3, wk, wct + (size_t)512 * 512);
    compose_w<<<dim3(8, 8), 256>>>(pe_w3, wv, wct + (size_t)1024 * 512);
    compose_bias<<<3, 512>>>(pe_b3, wq, wk, wv, bq, bk, bv, bc);

    // fused qkv projection from a2: [NCTX, 1536] fp32
    gemm_mma<0, 1><<<dim3(12, NCTX / 128), 256, GEMM_DSM>>>(a2h, a2l, 512, wct, bc, 1536, qkvf, nullptr, nullptr);

    // attention
    attn_kernel<<<BATCH, 256, attn_smem>>>(qkvf, sse, seg);

    // heads (clip)
    wt_conv<<<dim3(16, 16), 256>>>(wm, 512, wmt);
    wt_conv<<<dim3(16, 16), 256>>>(wlv, 512, wlvt);
    conv_hilo<<<BATCH * 512 / 4 / 256, 256>>>(seg, BATCH * 512 / 4, 9, 511, 512, 0, segh, segl);
    gemm_mma<2, 1><<<dim3(4, BATCH / 128), 256, GEMM_DSM>>>(segh, segl, 512, wmt, bm, 512, out_mean, nullptr, nullptr);
    gemm_mma<2, 1><<<dim3(4, BATCH / 128), 256, GEMM_DSM>>>(segh, segl, 512, wlvt, blv, 512, out_lv, nullptr, nullptr);

    // z
    z_kernel<<<BATCH, 256>>>(out_mean, out_lv, eps, out_z);

    // decoder weights
    wt_conv<<<dim3(16, 48), 256>>>(d_w1, 1536, dw1t);
    wt_conv<<<dim3(16, 16), 256>>>(d_w2, 512, dw2t);

    // decoder concat z part (cols 1024..1535, shared by both passes)
    conv_hilo<<<BATCH * 512 / 4 / 256, 256>>>(out_z, BATCH * 512 / 4, 9, 511, 1536, 1024, dcath, dcatl);

    // decoder (chosen)
    conv_hilo<<<BATCH * 1024 / 4 / 256, 256>>>(tc, BATCH * 1024 / 4, 10, 1023, 1536, 0, dcath, dcatl);
    gemm_mma<1, 0><<<dim3(4, BATCH / 128), 256, GEMM_DSM>>>(dcath, dcatl, 1536, dw1t, d_b1, 512, nullptr, d1h, d1l);
    gemm_mma<1, 1><<<dim3(4, BATCH / 128), 256, GEMM_DSM>>>(d1h, d1l, 512, dw2t, d_b2, 512, d2f, nullptr, nullptr);
    matvec_kernel<<<BATCH / 8, dim3(32, 8)>>>(d2f, d_w3, d_b3, out_rc);

    // decoder (rejected)
    conv_hilo<<<BATCH * 1024 / 4 / 256, 256>>>(tr, BATCH * 1024 / 4, 10, 1023, 1536, 0, dcath, dcatl);
    gemm_mma<1, 0><<<dim3(4, BATCH / 128), 256, GEMM_DSM>>>(dcath, dcatl, 1536, dw1t, d_b1, 512, nullptr, d1h, d1l);
    gemm_mma<1, 1><<<dim3(4, BATCH / 128), 256, GEMM_DSM>>>(d1h, d1l, 512, dw2t, d_b2, 512, d2f, nullptr, nullptr);
    matvec_kernel<<<BATCH / 8, dim3(32, 8)>>>(d2f, d_w3, d_b3, out_rr);

    (void)in_sizes; (void)n_in; (void)out_size;
}

// round 12
// speedup vs baseline: 1.6683x; 1.2236x over previous
#include <cuda_runtime.h>
#include <cuda_fp16.h>
#include <cstdint>

// ---------------- Problem constants ----------------
#define NCTX   65536
#define BATCH  2048
#define LMAX   48

// ---------------- low-level helpers ----------------
__device__ __forceinline__ uint32_t smem_u32(const void* p) {
    uint32_t a;
    asm("{ .reg .u64 t; cvta.to.shared.u64 t, %1; cvt.u32.u64 %0, t; }" : "=r"(a) : "l"(p));
    return a;
}
__device__ __forceinline__ void cp16(uint32_t s, const void* g) {
    asm volatile("cp.async.cg.shared.global [%0], [%1], 16;" :: "r"(s), "l"(g));
}
__device__ __forceinline__ void cp_commit() {
    asm volatile("cp.async.commit_group;" ::: "memory");
}
__device__ __forceinline__ void cp_wait1() {
    asm volatile("cp.async.wait_group 1;" ::: "memory");
}
__device__ __forceinline__ void cp_wait0() {
    asm volatile("cp.async.wait_group 0;" ::: "memory");
}
__device__ __forceinline__ void ldsm4(uint32_t& r0, uint32_t& r1, uint32_t& r2, uint32_t& r3,
                                      uint32_t addr) {
    asm volatile("ldmatrix.sync.aligned.m8n8.x4.shared.b16 {%0,%1,%2,%3}, [%4];"
                 : "=r"(r0), "=r"(r1), "=r"(r2), "=r"(r3) : "r"(addr));
}
__device__ __forceinline__ void mma16816(float* c, uint32_t a0, uint32_t a1, uint32_t a2,
                                         uint32_t a3, uint32_t b0, uint32_t b1) {
    asm volatile(
        "mma.sync.aligned.m16n8k16.row.col.f32.f16.f16.f32 "
        "{%0,%1,%2,%3}, {%4,%5,%6,%7}, {%8,%9}, {%0,%1,%2,%3};"
        : "+f"(c[0]), "+f"(c[1]), "+f"(c[2]), "+f"(c[3])
        : "r"(a0), "r"(a1), "r"(a2), "r"(a3), "r"(b0), "r"(b1));
}
__device__ __forceinline__ void hilo_split(float v, __half& h, __half& l) {
    h = __float2half_rn(v);
    l = __float2half_rn(v - __half2float(h));
}

// ---------------- Scratch (static device globals) ----------------
__device__ __half g_a1h[NCTX * 512],  g_a1l[NCTX * 512];
__device__ __half g_a2h[NCTX * 512],  g_a2l[NCTX * 512];
__device__ __half g_dcath[BATCH * 1536], g_dcatl[BATCH * 1536];
__device__ __half g_d1h[BATCH * 512], g_d1l[BATCH * 512];
__device__ __half g_segh[BATCH * 512], g_segl[BATCH * 512];
// transposed single-fp16 weights: Wt[n][k]
__device__ __half g_w1t[512 * 2048];
__device__ __half g_w2t[512 * 512];
__device__ __half g_wct[1536 * 512];   // composed pe_w3@Wqkv, transposed
__device__ __half g_wmt[512 * 512];
__device__ __half g_wlvt[512 * 512];
__device__ __half g_dw1t[512 * 1536];
__device__ __half g_dw2t[512 * 512];
__device__ float g_bc[1536];           // composed qkv bias
// fp32 buffers
__device__ float g_qkv[NCTX * 1536];
__device__ float g_seg[BATCH * 512];
__device__ float g_d2[BATCH * 512];

// ---------------- generic HMMA GEMM (fp16 2-pass, 3-stage) ----------------
#define STG_BYTES 30720u
#define GEMM_DSM  (3 * 30720)

template <int ACT, int OUTF32>
__global__ void __launch_bounds__(256, 2)
gemm_mma(const __half* __restrict__ Ahi, const __half* __restrict__ Alo, int K,
         const __half* __restrict__ Bt,
         const float* __restrict__ bias, int ldc,
         float* __restrict__ outF, __half* __restrict__ outHi, __half* __restrict__ outLo)
{
    extern __shared__ char dsm[];
    const uint32_t smBase = smem_u32(dsm);

    const int tid = threadIdx.x;
    const int lane = tid & 31;
    const int w = tid >> 5;
    const int warp_m = w >> 2;
    const int warp_n = w & 3;
    const int m0 = blockIdx.y * 128;
    const int n0 = blockIdx.x * 128;

    float c[4][4][4];
#pragma unroll
    for (int mi = 0; mi < 4; mi++)
#pragma unroll
        for (int ni = 0; ni < 4; ni++)
#pragma unroll
            for (int r = 0; r < 4; r++) c[mi][ni][r] = 0.f;

    const int nk = K >> 5;

    auto load_stage = [&](int s) {
        const uint32_t sb = smBase + (uint32_t)(s % 3) * STG_BYTES;
        const int k0 = s << 5;
#pragma unroll
        for (int j = 0; j < 2; j++) {
            int slot = tid + j * 256;
            int row = slot >> 2, k8 = slot & 3;
            uint32_t dst = sb + (uint32_t)row * 80u + (uint32_t)k8 * 16u;
            size_t ga = (size_t)(m0 + row) * K + k0 + k8 * 8;
            size_t gb = (size_t)(n0 + row) * K + k0 + k8 * 8;
            cp16(dst,           Ahi + ga);
            cp16(dst + 10240u,  Alo + ga);
            cp16(dst + 20480u,  Bt + gb);
        }
    };

    load_stage(0); cp_commit();
    load_stage(1); cp_commit();

    const int lr = lane & 15;
    const uint32_t lc16 = (uint32_t)(lane >> 4) * 16u;

    for (int s = 0; s < nk; s++) {
        cp_wait1();
        __syncthreads();
        if (s + 2 < nk) load_stage(s + 2);
        cp_commit();

        const uint32_t sb = smBase + (uint32_t)(s % 3) * STG_BYTES;
#pragma unroll
        for (int h = 0; h < 2; h++) {
            const uint32_t koff = (uint32_t)h * 32u + lc16;
            uint32_t ah[4][4], al[4][4], bb[2][4];
#pragma unroll
            for (int mi = 0; mi < 4; mi++) {
                uint32_t addr = sb + (uint32_t)((warp_m * 64 + mi * 16 + lr) * 80) + koff;
                ldsm4(ah[mi][0], ah[mi][1], ah[mi][2], ah[mi][3], addr);
                ldsm4(al[mi][0], al[mi][1], al[mi][2], al[mi][3], addr + 10240u);
            }
#pragma unroll
            for (int bt = 0; bt < 2; bt++) {
                uint32_t addr = sb + 20480u + (uint32_t)((warp_n * 32 + bt * 16 + lr) * 80) + koff;
                ldsm4(bb[bt][0], bb[bt][1], bb[bt][2], bb[bt][3], addr);
            }
#pragma unroll
            for (int ni = 0; ni < 4; ni++) {
                const int bt = ni >> 1, sl = ni & 1;
#pragma unroll
                for (int mi = 0; mi < 4; mi++)
                    mma16816(c[mi][ni], ah[mi][0], ah[mi][1], ah[mi][2], ah[mi][3],
                             bb[bt][sl], bb[bt][sl + 2]);
            }
#pragma unroll
            for (int ni = 0; ni < 4; ni++) {
                const int bt = ni >> 1, sl = ni & 1;
#pragma unroll
                for (int mi = 0; mi < 4; mi++)
                    mma16816(c[mi][ni], al[mi][0], al[mi][1], al[mi][2], al[mi][3],
                             bb[bt][sl], bb[bt][sl + 2]);
            }
        }
    }

#pragma unroll
    for (int mi = 0; mi < 4; mi++) {
        const int row = m0 + warp_m * 64 + mi * 16 + (lane >> 2);
#pragma unroll
        for (int ni = 0; ni < 4; ni++) {
            const int col = n0 + warp_n * 32 + ni * 8 + (lane & 3) * 2;
            const float b0 = bias[col], b1 = bias[col + 1];
            float v0 = c[mi][ni][0] + b0, v1 = c[mi][ni][1] + b1;
            float v2 = c[mi][ni][2] + b0, v3 = c[mi][ni][3] + b1;
            if (ACT == 1) {
                v0 = v0 > 0.f ? v0 : 0.2f * v0;
                v1 = v1 > 0.f ? v1 : 0.2f * v1;
                v2 = v2 > 0.f ? v2 : 0.2f * v2;
                v3 = v3 > 0.f ? v3 : 0.2f * v3;
            } else if (ACT == 2) {
                v0 = fminf(fmaxf(v0, -1.f), 1.f);
                v1 = fminf(fmaxf(v1, -1.f), 1.f);
                v2 = fminf(fmaxf(v2, -1.f), 1.f);
                v3 = fminf(fmaxf(v3, -1.f), 1.f);
            }
            if (OUTF32) {
                *(float2*)(outF + (size_t)row * ldc + col)       = make_float2(v0, v1);
                *(float2*)(outF + (size_t)(row + 8) * ldc + col) = make_float2(v2, v3);
            } else {
                __half h0, l0, h1, l1, h2, l2, h3, l3;
                hilo_split(v0, h0, l0); hilo_split(v1, h1, l1);
                hilo_split(v2, h2, l2); hilo_split(v3, h3, l3);
                *(__half2*)(outHi + (size_t)row * ldc + col)       = __halves2half2(h0, h1);
                *(__half2*)(outLo + (size_t)row * ldc + col)       = __halves2half2(l0, l1);
                *(__half2*)(outHi + (size_t)(row + 8) * ldc + col) = __halves2half2(h2, h3);
                *(__half2*)(outLo + (size_t)(row + 8) * ldc + col) = __halves2half2(l2, l3);
            }
        }
    }
}

// ---------------- layer-1 GEMM with fused fp32->hi/lo conversion ----------------
// A = concat(cc, cr) fp32 [NCTX, 2048]; K chunks of 32 never straddle the 1024 boundary.
// smem stage: [0,16384) A fp32 | [16384) Ahi 80B rows | [26624) Alo | [36864) B halves.
#define L1_STG 47104u
#define L1_DSM (2 * 47104)

__global__ void __launch_bounds__(256, 2)
gemm_l1(const float* __restrict__ cc, const float* __restrict__ cr,
        const __half* __restrict__ Bt, const float* __restrict__ bias,
        __half* __restrict__ outHi, __half* __restrict__ outLo)
{
    extern __shared__ char dsm[];
    const uint32_t smBase = smem_u32(dsm);
    const int K = 2048, nk = 64;

    const int tid = threadIdx.x;
    const int lane = tid & 31;
    const int w = tid >> 5;
    const int warp_m = w >> 2;
    const int warp_n = w & 3;
    const int m0 = blockIdx.y * 128;
    const int n0 = blockIdx.x * 128;

    float c[4][4][4];
#pragma unroll
    for (int mi = 0; mi < 4; mi++)
#pragma unroll
        for (int ni = 0; ni < 4; ni++)
#pragma unroll
            for (int r = 0; r < 4; r++) c[mi][ni][r] = 0.f;

    auto load_stage = [&](int s) {
        const uint32_t sb = smBase + (uint32_t)(s & 1) * L1_STG;
        const int k0 = s << 5;
        const float* A = (k0 < 1024) ? cc : cr;
        const int kc = k0 & 1023;
        // A fp32: 1024 slots (128 rows x 8 chunks of 16B)
#pragma unroll
        for (int j = 0; j < 4; j++) {
            int slot = tid + j * 256;
            int row = slot >> 3, c8 = slot & 7;
            cp16(sb + (uint32_t)row * 128u + (uint32_t)c8 * 16u,
                 A + (size_t)(m0 + row) * 1024 + kc + c8 * 4);
        }
        // B halves: 512 slots (128 rows x 4 chunks of 16B)
#pragma unroll
        for (int j = 0; j < 2; j++) {
            int slot = tid + j * 256;
            int row = slot >> 2, k8 = slot & 3;
            cp16(sb + 36864u + (uint32_t)row * 80u + (uint32_t)k8 * 16u,
                 Bt + (size_t)(n0 + row) * 2048 + k0 + k8 * 8);
        }
    };

    load_stage(0); cp_commit();

    const int lr = lane & 15;
    const uint32_t lc16 = (uint32_t)(lane >> 4) * 16u;

    for (int s = 0; s < nk; s++) {
        cp_wait0();                 // stage s fully resident
        __syncthreads();            // nobody still reading stage s-1 slot (= s+1 slot)
        if (s + 1 < nk) { load_stage(s + 1); cp_commit(); }

        const uint32_t sb = smBase + (uint32_t)(s & 1) * L1_STG;

        // convert A fp32 -> hi/lo halves (80B-stride layout for ldsm)
#pragma unroll
        for (int j = 0; j < 4; j++) {
            int slot = tid + j * 256;
            int row = slot >> 3, c8 = slot & 7;
            float4 v = *(const float4*)(dsm + (size_t)((s & 1) * L1_STG) + row * 128 + c8 * 16);
            __half h0, l0, h1, l1, h2, l2, h3, l3;
            hilo_split(v.x, h0, l0); hilo_split(v.y, h1, l1);
            hilo_split(v.z, h2, l2); hilo_split(v.w, h3, l3);
            char* hp = dsm + (size_t)((s & 1) * L1_STG) + 16384 + row * 80 + c8 * 8;
            char* lp = hp + 10240;
            *(__half2*)(hp)     = __halves2half2(h0, h1);
            *(__half2*)(hp + 4) = __halves2half2(h2, h3);
            *(__half2*)(lp)     = __halves2half2(l0, l1);
            *(__half2*)(lp + 4) = __halves2half2(l2, l3);
        }
        __syncthreads();

#pragma unroll
        for (int h = 0; h < 2; h++) {
            const uint32_t koff = (uint32_t)h * 32u + lc16;
            uint32_t ah[4][4], al[4][4], bb[2][4];
#pragma unroll
            for (int mi = 0; mi < 4; mi++) {
                uint32_t addr = sb + 16384u + (uint32_t)((warp_m * 64 + mi * 16 + lr) * 80) + koff;
                ldsm4(ah[mi][0], ah[mi][1], ah[mi][2], ah[mi][3], addr);
                ldsm4(al[mi][0], al[mi][1], al[mi][2], al[mi][3], addr + 10240u);
            }
#pragma unroll
            for (int bt = 0; bt < 2; bt++) {
                uint32_t addr = sb + 36864u + (uint32_t)((warp_n * 32 + bt * 16 + lr) * 80) + koff;
                ldsm4(bb[bt][0], bb[bt][1], bb[bt][2], bb[bt][3], addr);
            }
#pragma unroll
            for (int ni = 0; ni < 4; ni++) {
                const int bt = ni >> 1, sl = ni & 1;
#pragma unroll
                for (int mi = 0; mi < 4; mi++)
                    mma16816(c[mi][ni], ah[mi][0], ah[mi][1], ah[mi][2], ah[mi][3],
                             bb[bt][sl], bb[bt][sl + 2]);
            }
#pragma unroll
            for (int ni = 0; ni < 4; ni++) {
                const int bt = ni >> 1, sl = ni & 1;
#pragma unroll
                for (int mi = 0; mi < 4; mi++)
                    mma16816(c[mi][ni], al[mi][0], al[mi][1], al[mi][2], al[mi][3],
                             bb[bt][sl], bb[bt][sl + 2]);
            }
        }
    }

    // epilogue: lrelu, hi/lo out, ldc=512
#pragma unroll
    for (int mi = 0; mi < 4; mi++) {
        const int row = m0 + warp_m * 64 + mi * 16 + (lane >> 2);
#pragma unroll
        for (int ni = 0; ni < 4; ni++) {
            const int col = n0 + warp_n * 32 + ni * 8 + (lane & 3) * 2;
            const float b0 = bias[col], b1 = bias[col + 1];
            float v0 = c[mi][ni][0] + b0, v1 = c[mi][ni][1] + b1;
            float v2 = c[mi][ni][2] + b0, v3 = c[mi][ni][3] + b1;
            v0 = v0 > 0.f ? v0 : 0.2f * v0;
            v1 = v1 > 0.f ? v1 : 0.2f * v1;
            v2 = v2 > 0.f ? v2 : 0.2f * v2;
            v3 = v3 > 0.f ? v3 : 0.2f * v3;
            __half h0, l0, h1, l1, h2, l2, h3, l3;
            hilo_split(v0, h0, l0); hilo_split(v1, h1, l1);
            hilo_split(v2, h2, l2); hilo_split(v3, h3, l3);
            *(__half2*)(outHi + (size_t)row * 512 + col)       = __halves2half2(h0, h1);
            *(__half2*)(outLo + (size_t)row * 512 + col)       = __halves2half2(l0, l1);
            *(__half2*)(outHi + (size_t)(row + 8) * 512 + col) = __halves2half2(h2, h3);
            *(__half2*)(outLo + (size_t)(row + 8) * 512 + col) = __halves2half2(l2, l3);
        }
    }
}

// ---------------- fp32 -> hi/lo fp16 (strided into concat buffer) ----------------
__global__ void __launch_bounds__(256)
conv_hilo(const float* __restrict__ src, int total4, int kshift, int kmask,
          int dstStride, int dstOff,
          __half* __restrict__ h, __half* __restrict__ l)
{
    int i = blockIdx.x * 256 + threadIdx.x;
    if (i >= total4) return;
    int e = i << 2;
    int row = e >> kshift, col = e & kmask;
    float4 v = *(const float4*)(src + e);
    size_t o = (size_t)row * dstStride + dstOff + col;
    __half h0, l0, h1, l1, h2, l2, h3, l3;
    hilo_split(v.x, h0, l0); hilo_split(v.y, h1, l1);
    hilo_split(v.z, h2, l2); hilo_split(v.w, h3, l3);
    __half2* hp = (__half2*)(h + o);
    __half2* lp = (__half2*)(l + o);
    hp[0] = __halves2half2(h0, h1); hp[1] = __halves2half2(h2, h3);
    lp[0] = __halves2half2(l0, l1); lp[1] = __halves2half2(l2, l3);
}

// ---------------- weight transpose + fp16: W[K,512] -> Wt[512,K] ----------------
__global__ void __launch_bounds__(256)
wt_conv(const float* __restrict__ W, int K, __half* __restrict__ T)
{
    __shared__ float t[32][33];
    const int nb = blockIdx.x * 32, kb = blockIdx.y * 32;
    const int tx = threadIdx.x & 31, ty = threadIdx.x >> 5;
#pragma unroll
    for (int i = 0; i < 32; i += 8)
        t[ty + i][tx] = W[(size_t)(kb + ty + i) * 512 + nb + tx];
    __syncthreads();
#pragma unroll
    for (int i = 0; i < 32; i += 8)
        T[(size_t)(nb + ty + i) * K + kb + tx] = __float2half_rn(t[tx][ty + i]);
}

// ---------------- weight composition: C = A(512x512)@B(512x512) -> T[n*512+i] fp16 ----------------
__global__ void __launch_bounds__(256)
compose_w(const float* __restrict__ A, const float* __restrict__ B, __half* __restrict__ T)
{
    __shared__ float As[64][17];
    __shared__ float Bs[16][68];
    const int i0 = blockIdx.y * 64, nb0 = blockIdx.x * 64;
    const int tx = threadIdx.x & 15, ty = threadIdx.x >> 4;
    float acc[4][4] = {};
    for (int j0 = 0; j0 < 512; j0 += 16) {
        for (int t = threadIdx.x; t < 1024; t += 256) {
            int r = t >> 4, jj = t & 15;
            As[r][jj] = A[(size_t)(i0 + r) * 512 + j0 + jj];
        }
        for (int t = threadIdx.x; t < 1024; t += 256) {
            int r = t >> 6, nn = t & 63;
            Bs[r][nn] = B[(size_t)(j0 + r) * 512 + nb0 + nn];
        }
        __syncthreads();
#pragma unroll
        for (int jj = 0; jj < 16; jj++) {
            float a[4], b[4];
#pragma unroll
            for (int u = 0; u < 4; u++) a[u] = As[ty * 4 + u][jj];
#pragma unroll
            for (int u = 0; u < 4; u++) b[u] = Bs[jj][tx * 4 + u];
#pragma unroll
            for (int u = 0; u < 4; u++)
#pragma unroll
                for (int v = 0; v < 4; v++) acc[u][v] += a[u] * b[v];
        }
        __syncthreads();
    }
#pragma unroll
    for (int u = 0; u < 4; u++)
#pragma unroll
        for (int v = 0; v < 4; v++) {
            int i = i0 + ty * 4 + u, n = nb0 + tx * 4 + v;
            T[(size_t)n * 512 + i] = __float2half_rn(acc[u][v]);
        }
}

// ---------------- composed qkv bias ----------------
__global__ void __launch_bounds__(512)
compose_bias(const float* __restrict__ b3,
             const float* __restrict__ Bq, const float* __restrict__ Bk, const float* __restrict__ Bv,
             const float* __restrict__ bq, const float* __restrict__ bk, const float* __restrict__ bv,
             float* __restrict__ bc)
{
    const int seg = blockIdx.x, n = threadIdx.x;
    const float* B = seg == 0 ? Bq : seg == 1 ? Bk : Bv;
    const float* bb = seg == 0 ? bq : seg == 1 ? bk : bv;
    float s = bb[n];
    for (int j = 0; j < 512; j++) s += b3[j] * B[(size_t)j * 512 + n];
    bc[seg * 512 + n] = s;
}

// ---------------- Attention v2: k-only staging, q in registers, 2 CTAs/SM ----------------
#define ATT_DSM (LMAX * 512 * 4)   // 98304: k tile fp32

__global__ void __launch_bounds__(256, 2)
attn_kernel(const float* __restrict__ qkv, const int* __restrict__ sse,
            float* __restrict__ seg_out)
{
    extern __shared__ float ks[];            // [len][512]
    __shared__ float scores[LMAX][LMAX];
    __shared__ float colsum[LMAX];

    const int b = blockIdx.x;
    const int tid = threadIdx.x;
    const int warp = tid >> 5, lane = tid & 31;
    const int start = sse[2 * b];
    const int len = sse[2 * b + 1] - start;

    const float4* g = (const float4*)(qkv + (size_t)start * 1536);   // row stride 384 float4

    // stage k only
    {
        float4* k4 = (float4*)ks;
        int tot = len * 128;
        for (int i = tid; i < tot; i += 256) {
            int row = i >> 7, cc = i & 127;
            k4[i] = g[row * 384 + 128 + cc];
        }
    }
    __syncthreads();

    // scores: warp per query row; q held in registers (loaded once per row from global)
    {
        const float scale = 0.044194173824159216f;   // 1/sqrt(512)
        const float4* k4 = (const float4*)ks;
        for (int l = warp; l < len; l += 8) {
            float4 q[4];
            const float4* qr = g + l * 384 + lane;
#pragma unroll
            for (int i = 0; i < 4; i++) q[i] = __ldg(qr + i * 32);
            for (int m = 0; m < len; m++) {
                const float4* kr = k4 + m * 128 + lane;
                float s = 0.f;
#pragma unroll
                for (int i = 0; i < 4; i++) {
                    float4 kv = kr[i * 32];
                    s += q[i].x * kv.x + q[i].y * kv.y + q[i].z * kv.z + q[i].w * kv.w;
                }
#pragma unroll
                for (int off = 16; off > 0; off >>= 1)
                    s += __shfl_xor_sync(0xffffffffu, s, off);
                if (lane == 0) scores[l][m] = s * scale;
            }
        }
    }
    __syncthreads();

    if (tid < len) {
        float mx = -1e30f;
        for (int m = 0; m < len; m++) mx = fmaxf(mx, scores[tid][m]);
        float sum = 0.f;
        for (int m = 0; m < len; m++) {
            float e = __expf(scores[tid][m] - mx);
            scores[tid][m] = e; sum += e;
        }
        float inv = 1.f / sum;
        for (int m = 0; m < len; m++) scores[tid][m] *= inv;
    }
    __syncthreads();

    if (tid < len) {
        float cs = 0.f;
        for (int l = 0; l < len; l++) cs += scores[l][tid];
        colsum[tid] = cs;
    }
    __syncthreads();

    const float invlen = 1.f / (float)len;
    for (int d = tid; d < 512; d += 256) {
        float s = 0.f;
        for (int m = 0; m < len; m++)
            s += colsum[m] * qkv[(size_t)(start + m) * 1536 + 1024 + d];
        seg_out[(size_t)b * 512 + d] = s * invlen;
    }
}

// ---------------- z = normalize(mean + exp(0.5*lv)*eps) * sqrt(512) ----------------
__global__ void __launch_bounds__(256)
z_kernel(const float* __restrict__ mean, const float* __restrict__ lv,
         const float* __restrict__ eps, float* __restrict__ zout)
{
    __shared__ float red[256];
    const int b = blockIdx.x, tid = threadIdx.x;
    float zi[2];
    float ss = 0.f;
#pragma unroll
    for (int j = 0; j < 2; j++) {
        int d = tid + 256 * j;
        size_t idx = (size_t)b * 512 + d;
        float z = mean[idx] + __expf(0.5f * lv[idx]) * eps[idx];
        zi[j] = z; ss += z * z;
    }
    red[tid] = ss;
    __syncthreads();
    for (int s = 128; s > 0; s >>= 1) {
        if (tid < s) red[tid] += red[tid + s];
        __syncthreads();
    }
    float denom = fmaxf(sqrtf(red[0]), 1e-12f);
    float fac = 22.627416997969522f / denom;
#pragma unroll
    for (int j = 0; j < 2; j++) {
        int d = tid + 256 * j;
        zout[(size_t)b * 512 + d] = zi[j] * fac;
    }
}

// ---------------- final head matvec ----------------
__global__ void __launch_bounds__(256)
matvec_kernel(const float* __restrict__ A, const float* __restrict__ w,
              const float* __restrict__ b, float* __restrict__ out)
{
    const int lane = threadIdx.x;
    const int row = blockIdx.x * 8 + threadIdx.y;
    float s = 0.f;
    for (int k = lane; k < 512; k += 32)
        s += A[(size_t)row * 512 + k] * w[k];
#pragma unroll
    for (int off = 16; off > 0; off >>= 1)
        s += __shfl_xor_sync(0xffffffffu, s, off);
    if (lane == 0) out[row] = s + b[0];
}

// ---------------- host side ----------------
extern "C" void kernel_launch(void* const* d_in, const int* in_sizes, int n_in,
                              void* d_out, int out_size)
{
    const float* tc    = (const float*)d_in[0];
    const float* tr    = (const float*)d_in[1];
    const float* cc    = (const float*)d_in[2];
    const float* cr    = (const float*)d_in[3];
    const float* eps   = (const float*)d_in[4];
    const float* pe_w1 = (const float*)d_in[5];
    const float* pe_b1 = (const float*)d_in[6];
    const float* pe_w2 = (const float*)d_in[7];
    const float* pe_b2 = (const float*)d_in[8];
    const float* pe_w3 = (const float*)d_in[9];
    const float* pe_b3 = (const float*)d_in[10];
    const float* wq    = (const float*)d_in[11];
    const float* bq    = (const float*)d_in[12];
    const float* wk    = (const float*)d_in[13];
    const float* bk    = (const float*)d_in[14];
    const float* wv    = (const float*)d_in[15];
    const float* bv    = (const float*)d_in[16];
    const float* wm    = (const float*)d_in[17];
    const float* bm    = (const float*)d_in[18];
    const float* wlv   = (const float*)d_in[19];
    const float* blv   = (const float*)d_in[20];
    const float* d_w1  = (const float*)d_in[21];
    const float* d_b1  = (const float*)d_in[22];
    const float* d_w2  = (const float*)d_in[23];
    const float* d_b2  = (const float*)d_in[24];
    const float* d_w3  = (const float*)d_in[25];
    const float* d_b3  = (const float*)d_in[26];
    const int*   sse   = (const int*)d_in[27];

    float* out = (float*)d_out;
    float* out_rc   = out;
    float* out_rr   = out + BATCH;
    float* out_mean = out + 2 * BATCH;
    float* out_lv   = out_mean + BATCH * 512;
    float* out_z    = out_lv + BATCH * 512;

    __half *a1h, *a1l, *a2h, *a2l;
    __half *dcath, *dcatl, *d1h, *d1l, *segh, *segl;
    __half *w1t, *w2t, *wct, *wmt, *wlvt, *dw1t, *dw2t;
    float *qkvf, *seg, *d2f, *bc;
    cudaGetSymbolAddress((void**)&a1h, g_a1h);     cudaGetSymbolAddress((void**)&a1l, g_a1l);
    cudaGetSymbolAddress((void**)&a2h, g_a2h);     cudaGetSymbolAddress((void**)&a2l, g_a2l);
    cudaGetSymbolAddress((void**)&dcath, g_dcath); cudaGetSymbolAddress((void**)&dcatl, g_dcatl);
    cudaGetSymbolAddress((void**)&d1h, g_d1h);     cudaGetSymbolAddress((void**)&d1l, g_d1l);
    cudaGetSymbolAddress((void**)&segh, g_segh);   cudaGetSymbolAddress((void**)&segl, g_segl);
    cudaGetSymbolAddress((void**)&w1t, g_w1t);
    cudaGetSymbolAddress((void**)&w2t, g_w2t);
    cudaGetSymbolAddress((void**)&wct, g_wct);
    cudaGetSymbolAddress((void**)&wmt, g_wmt);
    cudaGetSymbolAddress((void**)&wlvt, g_wlvt);
    cudaGetSymbolAddress((void**)&dw1t, g_dw1t);
    cudaGetSymbolAddress((void**)&dw2t, g_dw2t);
    cudaGetSymbolAddress((void**)&qkvf, g_qkv);
    cudaGetSymbolAddress((void**)&seg, g_seg);
    cudaGetSymbolAddress((void**)&d2f, g_d2);
    cudaGetSymbolAddress((void**)&bc, g_bc);

    cudaFuncSetAttribute(gemm_l1, cudaFuncAttributeMaxDynamicSharedMemorySize, L1_DSM);
    cudaFuncSetAttribute(gemm_mma<0, 1>, cudaFuncAttributeMaxDynamicSharedMemorySize, GEMM_DSM);
    cudaFuncSetAttribute(gemm_mma<1, 0>, cudaFuncAttributeMaxDynamicSharedMemorySize, GEMM_DSM);
    cudaFuncSetAttribute(gemm_mma<1, 1>, cudaFuncAttributeMaxDynamicSharedMemorySize, GEMM_DSM);
    cudaFuncSetAttribute(gemm_mma<2, 1>, cudaFuncAttributeMaxDynamicSharedMemorySize, GEMM_DSM);
    cudaFuncSetAttribute(attn_kernel, cudaFuncAttributeMaxDynamicSharedMemorySize, ATT_DSM);

    // layer-1 weight, then layer-1 GEMM with fused input conversion
    wt_conv<<<dim3(16, 64), 256>>>(pe_w1, 2048, w1t);
    gemm_l1<<<dim3(4, NCTX / 128), 256, L1_DSM>>>(cc, cr, w1t, pe_b1, a1h, a1l);

    wt_conv<<<dim3(16, 16), 256>>>(pe_w2, 512, w2t);

    // layer 2 (K=512)
    gemm_mma<1, 0><<<dim3(4, NCTX / 128), 256, GEMM_DSM>>>(a1h, a1l, 512, w2t, pe_b2, 512, nullptr, a2h, a2l);

    // compose pe_w3 into qkv weights + bias
    compose_w<<<dim3(8, 8), 256>>>(pe_w3, wq, wct);
    compose_w<<<dim3(8, 8), 256>>>(pe_w3, wk, wct + (size_t)512 * 512);
    compose_w<<<dim3(8, 8), 256>>>(pe_w3, wv, wct + (size_t)1024 * 512);
    compose_bias<<<3, 512>>>(pe_b3, wq, wk, wv, bq, bk, bv, bc);

    // fused qkv projection from a2: [NCTX, 1536] fp32
    gemm_mma<0, 1><<<dim3(12, NCTX / 128), 256, GEMM_DSM>>>(a2h, a2l, 512, wct, bc, 1536, qkvf, nullptr, nullptr);

    // attention
    attn_kernel<<<BATCH, 256, ATT_DSM>>>(qkvf, sse, seg);

    // heads (clip)
    wt_conv<<<dim3(16, 16), 256>>>(wm, 512, wmt);
    wt_conv<<<dim3(16, 16), 256>>>(wlv, 512, wlvt);
    conv_hilo<<<BATCH * 512 / 4 / 256, 256>>>(seg, BATCH * 512 / 4, 9, 511, 512, 0, segh, segl);
    gemm_mma<2, 1><<<dim3(4, BATCH / 128), 256, GEMM_DSM>>>(segh, segl, 512, wmt, bm, 512, out_mean, nullptr, nullptr);
    gemm_mma<2, 1><<<dim3(4, BATCH / 128), 256, GEMM_DSM>>>(segh, segl, 512, wlvt, blv, 512, out_lv, nullptr, nullptr);

    // z
    z_kernel<<<BATCH, 256>>>(out_mean, out_lv, eps, out_z);

    // decoder weights
    wt_conv<<<dim3(16, 48), 256>>>(d_w1, 1536, dw1t);
    wt_conv<<<dim3(16, 16), 256>>>(d_w2, 512, dw2t);

    // decoder concat z part (cols 1024..1535, shared by both passes)
    conv_hilo<<<BATCH * 512 / 4 / 256, 256>>>(out_z, BATCH * 512 / 4, 9, 511, 1536, 1024, dcath, dcatl);

    // decoder (chosen)
    conv_hilo<<<BATCH * 1024 / 4 / 256, 256>>>(tc, BATCH * 1024 / 4, 10, 1023, 1536, 0, dcath, dcatl);
    gemm_mma<1, 0><<<dim3(4, BATCH / 128), 256, GEMM_DSM>>>(dcath, dcatl, 1536, dw1t, d_b1, 512, nullptr, d1h, d1l);
    gemm_mma<1, 1><<<dim3(4, BATCH / 128), 256, GEMM_DSM>>>(d1h, d1l, 512, dw2t, d_b2, 512, d2f, nullptr, nullptr);
    matvec_kernel<<<BATCH / 8, dim3(32, 8)>>>(d2f, d_w3, d_b3, out_rc);

    // decoder (rejected)
    conv_hilo<<<BATCH * 1024 / 4 / 256, 256>>>(tr, BATCH * 1024 / 4, 10, 1023, 1536, 0, dcath, dcatl);
    gemm_mma<1, 0><<<dim3(4, BATCH / 128), 256, GEMM_DSM>>>(dcath, dcatl, 1536, dw1t, d_b1, 512, nullptr, d1h, d1l);
    gemm_mma<1, 1><<<dim3(4, BATCH / 128), 256, GEMM_DSM>>>(d1h, d1l, 512, dw2t, d_b2, 512, d2f, nullptr, nullptr);
    matvec_kernel<<<BATCH / 8, dim3(32, 8)>>>(d2f, d_w3, d_b3, out_rr);

    (void)in_sizes; (void)n_in; (void)out_size;
}

// round 14
// speedup vs baseline: 1.7382x; 1.0419x over previous
#include <cuda_runtime.h>
#include <cuda_fp16.h>
#include <cstdint>

// ---------------- Problem constants ----------------
#define NCTX   65536
#define BATCH  2048
#define LMAX   48

// ---------------- low-level helpers ----------------
__device__ __forceinline__ uint32_t smem_u32(const void* p) {
    uint32_t a;
    asm("{ .reg .u64 t; cvta.to.shared.u64 t, %1; cvt.u32.u64 %0, t; }" : "=r"(a) : "l"(p));
    return a;
}
__device__ __forceinline__ void cp16(uint32_t s, const void* g) {
    asm volatile("cp.async.cg.shared.global [%0], [%1], 16;" :: "r"(s), "l"(g));
}
__device__ __forceinline__ void cp_commit() {
    asm volatile("cp.async.commit_group;" ::: "memory");
}
__device__ __forceinline__ void cp_wait1() {
    asm volatile("cp.async.wait_group 1;" ::: "memory");
}
__device__ __forceinline__ void cp_wait0() {
    asm volatile("cp.async.wait_group 0;" ::: "memory");
}
__device__ __forceinline__ void ldsm4(uint32_t& r0, uint32_t& r1, uint32_t& r2, uint32_t& r3,
                                      uint32_t addr) {
    asm volatile("ldmatrix.sync.aligned.m8n8.x4.shared.b16 {%0,%1,%2,%3}, [%4];"
                 : "=r"(r0), "=r"(r1), "=r"(r2), "=r"(r3) : "r"(addr));
}
__device__ __forceinline__ void mma16816(float* c, uint32_t a0, uint32_t a1, uint32_t a2,
                                         uint32_t a3, uint32_t b0, uint32_t b1) {
    asm volatile(
        "mma.sync.aligned.m16n8k16.row.col.f32.f16.f16.f32 "
        "{%0,%1,%2,%3}, {%4,%5,%6,%7}, {%8,%9}, {%0,%1,%2,%3};"
        : "+f"(c[0]), "+f"(c[1]), "+f"(c[2]), "+f"(c[3])
        : "r"(a0), "r"(a1), "r"(a2), "r"(a3), "r"(b0), "r"(b1));
}
__device__ __forceinline__ void hilo_split(float v, __half& h, __half& l) {
    h = __float2half_rn(v);
    l = __float2half_rn(v - __half2float(h));
}

// ---------------- Scratch (static device globals) ----------------
__device__ __half g_a1h[NCTX * 512],  g_a1l[NCTX * 512];
__device__ __half g_a2h[NCTX * 512],  g_a2l[NCTX * 512];
__device__ __half g_dcath[2 * BATCH * 1536], g_dcatl[2 * BATCH * 1536];  // [4096, 1536]
__device__ __half g_d1h[2 * BATCH * 512], g_d1l[2 * BATCH * 512];
__device__ __half g_segh[BATCH * 512], g_segl[BATCH * 512];
// transposed single-fp16 weights: Wt[n][k]
__device__ __half g_w1t[512 * 2048];
__device__ __half g_w2t[512 * 512];
__device__ __half g_wct[1536 * 512];      // composed pe_w3@Wqkv
__device__ __half g_wht[1024 * 512];      // packed wm | wlv
__device__ __half g_dw1t[512 * 1536];
__device__ __half g_dw2t[512 * 512];
__device__ float g_bc[1536];              // composed qkv bias
__device__ float g_bh[1024];              // packed bm | blv
// fp32 buffers
__device__ float g_qkv[NCTX * 1536];
__device__ float g_d2[2 * BATCH * 512];

// ---------------- generic HMMA GEMM (fp16 2-pass, 3-stage) ----------------
// OUTMODE: 0 = hi/lo fp16 (ldc), 1 = fp32 (ldc), 2 = heads split fp32 (N=1024 -> two blocks)
#define STG_BYTES 30720u
#define GEMM_DSM  (3 * 30720)

template <int ACT, int OUTMODE>
__global__ void __launch_bounds__(256, 2)
gemm_mma(const __half* __restrict__ Ahi, const __half* __restrict__ Alo, int K,
         const __half* __restrict__ Bt,
         const float* __restrict__ bias, int ldc,
         float* __restrict__ outF, __half* __restrict__ outHi, __half* __restrict__ outLo)
{
    extern __shared__ char dsm[];
    const uint32_t smBase = smem_u32(dsm);

    const int tid = threadIdx.x;
    const int lane = tid & 31;
    const int w = tid >> 5;
    const int warp_m = w >> 2;
    const int warp_n = w & 3;
    const int m0 = blockIdx.y * 128;
    const int n0 = blockIdx.x * 128;

    float c[4][4][4];
#pragma unroll
    for (int mi = 0; mi < 4; mi++)
#pragma unroll
        for (int ni = 0; ni < 4; ni++)
#pragma unroll
            for (int r = 0; r < 4; r++) c[mi][ni][r] = 0.f;

    const int nk = K >> 5;

    auto load_stage = [&](int s) {
        const uint32_t sb = smBase + (uint32_t)(s % 3) * STG_BYTES;
        const int k0 = s << 5;
#pragma unroll
        for (int j = 0; j < 2; j++) {
            int slot = tid + j * 256;
            int row = slot >> 2, k8 = slot & 3;
            uint32_t dst = sb + (uint32_t)row * 80u + (uint32_t)k8 * 16u;
            size_t ga = (size_t)(m0 + row) * K + k0 + k8 * 8;
            size_t gb = (size_t)(n0 + row) * K + k0 + k8 * 8;
            cp16(dst,           Ahi + ga);
            cp16(dst + 10240u,  Alo + ga);
            cp16(dst + 20480u,  Bt + gb);
        }
    };

    load_stage(0); cp_commit();
    load_stage(1); cp_commit();

    const int lr = lane & 15;
    const uint32_t lc16 = (uint32_t)(lane >> 4) * 16u;

    for (int s = 0; s < nk; s++) {
        cp_wait1();
        __syncthreads();
        if (s + 2 < nk) load_stage(s + 2);
        cp_commit();

        const uint32_t sb = smBase + (uint32_t)(s % 3) * STG_BYTES;
#pragma unroll
        for (int h = 0; h < 2; h++) {
            const uint32_t koff = (uint32_t)h * 32u + lc16;
            uint32_t ah[4][4], al[4][4], bb[2][4];
#pragma unroll
            for (int mi = 0; mi < 4; mi++) {
                uint32_t addr = sb + (uint32_t)((warp_m * 64 + mi * 16 + lr) * 80) + koff;
                ldsm4(ah[mi][0], ah[mi][1], ah[mi][2], ah[mi][3], addr);
                ldsm4(al[mi][0], al[mi][1], al[mi][2], al[mi][3], addr + 10240u);
            }
#pragma unroll
            for (int bt = 0; bt < 2; bt++) {
                uint32_t addr = sb + 20480u + (uint32_t)((warp_n * 32 + bt * 16 + lr) * 80) + koff;
                ldsm4(bb[bt][0], bb[bt][1], bb[bt][2], bb[bt][3], addr);
            }
#pragma unroll
            for (int ni = 0; ni < 4; ni++) {
                const int bt = ni >> 1, sl = ni & 1;
#pragma unroll
                for (int mi = 0; mi < 4; mi++)
                    mma16816(c[mi][ni], ah[mi][0], ah[mi][1], ah[mi][2], ah[mi][3],
                             bb[bt][sl], bb[bt][sl + 2]);
            }
#pragma unroll
            for (int ni = 0; ni < 4; ni++) {
                const int bt = ni >> 1, sl = ni & 1;
#pragma unroll
                for (int mi = 0; mi < 4; mi++)
                    mma16816(c[mi][ni], al[mi][0], al[mi][1], al[mi][2], al[mi][3],
                             bb[bt][sl], bb[bt][sl + 2]);
            }
        }
    }

#pragma unroll
    for (int mi = 0; mi < 4; mi++) {
        const int row = m0 + warp_m * 64 + mi * 16 + (lane >> 2);
#pragma unroll
        for (int ni = 0; ni < 4; ni++) {
            const int col = n0 + warp_n * 32 + ni * 8 + (lane & 3) * 2;
            const float b0 = bias[col], b1 = bias[col + 1];
            float v0 = c[mi][ni][0] + b0, v1 = c[mi][ni][1] + b1;
            float v2 = c[mi][ni][2] + b0, v3 = c[mi][ni][3] + b1;
            if (ACT == 1) {
                v0 = v0 > 0.f ? v0 : 0.2f * v0;
                v1 = v1 > 0.f ? v1 : 0.2f * v1;
                v2 = v2 > 0.f ? v2 : 0.2f * v2;
                v3 = v3 > 0.f ? v3 : 0.2f * v3;
            } else if (ACT == 2) {
                v0 = fminf(fmaxf(v0, -1.f), 1.f);
                v1 = fminf(fmaxf(v1, -1.f), 1.f);
                v2 = fminf(fmaxf(v2, -1.f), 1.f);
                v3 = fminf(fmaxf(v3, -1.f), 1.f);
            }
            if (OUTMODE == 1) {
                *(float2*)(outF + (size_t)row * ldc + col)       = make_float2(v0, v1);
                *(float2*)(outF + (size_t)(row + 8) * ldc + col) = make_float2(v2, v3);
            } else if (OUTMODE == 2) {
                // N=1024: col<512 -> block 0 (mean), col>=512 -> block 1 (+BATCH*512)
                size_t base = (size_t)(col >> 9) * ((size_t)BATCH * 512) + (col & 511);
                *(float2*)(outF + base + (size_t)row * 512)       = make_float2(v0, v1);
                *(float2*)(outF + base + (size_t)(row + 8) * 512) = make_float2(v2, v3);
            } else {
                __half h0, l0, h1, l1, h2, l2, h3, l3;
                hilo_split(v0, h0, l0); hilo_split(v1, h1, l1);
                hilo_split(v2, h2, l2); hilo_split(v3, h3, l3);
                *(__half2*)(outHi + (size_t)row * ldc + col)       = __halves2half2(h0, h1);
                *(__half2*)(outLo + (size_t)row * ldc + col)       = __halves2half2(l0, l1);
                *(__half2*)(outHi + (size_t)(row + 8) * ldc + col) = __halves2half2(h2, h3);
                *(__half2*)(outLo + (size_t)(row + 8) * ldc + col) = __halves2half2(l2, l3);
            }
        }
    }
}

// ---------------- layer-1 GEMM with fused fp32->hi/lo conversion ----------------
#define L1_STG 47104u
#define L1_DSM (2 * 47104)

__global__ void __launch_bounds__(256, 2)
gemm_l1(const float* __restrict__ cc, const float* __restrict__ cr,
        const __half* __restrict__ Bt, const float* __restrict__ bias,
        __half* __restrict__ outHi, __half* __restrict__ outLo)
{
    extern __shared__ char dsm[];
    const uint32_t smBase = smem_u32(dsm);
    const int K = 2048, nk = 64;

    const int tid = threadIdx.x;
    const int lane = tid & 31;
    const int w = tid >> 5;
    const int warp_m = w >> 2;
    const int warp_n = w & 3;
    const int m0 = blockIdx.y * 128;
    const int n0 = blockIdx.x * 128;

    float c[4][4][4];
#pragma unroll
    for (int mi = 0; mi < 4; mi++)
#pragma unroll
        for (int ni = 0; ni < 4; ni++)
#pragma unroll
            for (int r = 0; r < 4; r++) c[mi][ni][r] = 0.f;

    auto load_stage = [&](int s) {
        const uint32_t sb = smBase + (uint32_t)(s & 1) * L1_STG;
        const int k0 = s << 5;
        const float* A = (k0 < 1024) ? cc : cr;
        const int kc = k0 & 1023;
#pragma unroll
        for (int j = 0; j < 4; j++) {
            int slot = tid + j * 256;
            int row = slot >> 3, c8 = slot & 7;
            cp16(sb + (uint32_t)row * 128u + (uint32_t)c8 * 16u,
                 A + (size_t)(m0 + row) * 1024 + kc + c8 * 4);
        }
#pragma unroll
        for (int j = 0; j < 2; j++) {
            int slot = tid + j * 256;
            int row = slot >> 2, k8 = slot & 3;
            cp16(sb + 36864u + (uint32_t)row * 80u + (uint32_t)k8 * 16u,
                 Bt + (size_t)(n0 + row) * 2048 + k0 + k8 * 8);
        }
    };

    load_stage(0); cp_commit();

    const int lr = lane & 15;
    const uint32_t lc16 = (uint32_t)(lane >> 4) * 16u;

    for (int s = 0; s < nk; s++) {
        cp_wait0();
        __syncthreads();
        if (s + 1 < nk) { load_stage(s + 1); cp_commit(); }

        const uint32_t sb = smBase + (uint32_t)(s & 1) * L1_STG;

#pragma unroll
        for (int j = 0; j < 4; j++) {
            int slot = tid + j * 256;
            int row = slot >> 3, c8 = slot & 7;
            float4 v = *(const float4*)(dsm + (size_t)((s & 1) * L1_STG) + row * 128 + c8 * 16);
            __half h0, l0, h1, l1, h2, l2, h3, l3;
            hilo_split(v.x, h0, l0); hilo_split(v.y, h1, l1);
            hilo_split(v.z, h2, l2); hilo_split(v.w, h3, l3);
            char* hp = dsm + (size_t)((s & 1) * L1_STG) + 16384 + row * 80 + c8 * 8;
            char* lp = hp + 10240;
            *(__half2*)(hp)     = __halves2half2(h0, h1);
            *(__half2*)(hp + 4) = __halves2half2(h2, h3);
            *(__half2*)(lp)     = __halves2half2(l0, l1);
            *(__half2*)(lp + 4) = __halves2half2(l2, l3);
        }
        __syncthreads();

#pragma unroll
        for (int h = 0; h < 2; h++) {
            const uint32_t koff = (uint32_t)h * 32u + lc16;
            uint32_t ah[4][4], al[4][4], bb[2][4];
#pragma unroll
            for (int mi = 0; mi < 4; mi++) {
                uint32_t addr = sb + 16384u + (uint32_t)((warp_m * 64 + mi * 16 + lr) * 80) + koff;
                ldsm4(ah[mi][0], ah[mi][1], ah[mi][2], ah[mi][3], addr);
                ldsm4(al[mi][0], al[mi][1], al[mi][2], al[mi][3], addr + 10240u);
            }
#pragma unroll
            for (int bt = 0; bt < 2; bt++) {
                uint32_t addr = sb + 36864u + (uint32_t)((warp_n * 32 + bt * 16 + lr) * 80) + koff;
                ldsm4(bb[bt][0], bb[bt][1], bb[bt][2], bb[bt][3], addr);
            }
#pragma unroll
            for (int ni = 0; ni < 4; ni++) {
                const int bt = ni >> 1, sl = ni & 1;
#pragma unroll
                for (int mi = 0; mi < 4; mi++)
                    mma16816(c[mi][ni], ah[mi][0], ah[mi][1], ah[mi][2], ah[mi][3],
                             bb[bt][sl], bb[bt][sl + 2]);
            }
#pragma unroll
            for (int ni = 0; ni < 4; ni++) {
                const int bt = ni >> 1, sl = ni & 1;
#pragma unroll
                for (int mi = 0; mi < 4; mi++)
                    mma16816(c[mi][ni], al[mi][0], al[mi][1], al[mi][2], al[mi][3],
                             bb[bt][sl], bb[bt][sl + 2]);
            }
        }
    }

#pragma unroll
    for (int mi = 0; mi < 4; mi++) {
        const int row = m0 + warp_m * 64 + mi * 16 + (lane >> 2);
#pragma unroll
        for (int ni = 0; ni < 4; ni++) {
            const int col = n0 + warp_n * 32 + ni * 8 + (lane & 3) * 2;
            const float b0 = bias[col], b1 = bias[col + 1];
            float v0 = c[mi][ni][0] + b0, v1 = c[mi][ni][1] + b1;
            float v2 = c[mi][ni][2] + b0, v3 = c[mi][ni][3] + b1;
            v0 = v0 > 0.f ? v0 : 0.2f * v0;
            v1 = v1 > 0.f ? v1 : 0.2f * v1;
            v2 = v2 > 0.f ? v2 : 0.2f * v2;
            v3 = v3 > 0.f ? v3 : 0.2f * v3;
            __half h0, l0, h1, l1, h2, l2, h3, l3;
            hilo_split(v0, h0, l0); hilo_split(v1, h1, l1);
            hilo_split(v2, h2, l2); hilo_split(v3, h3, l3);
            *(__half2*)(outHi + (size_t)row * 512 + col)       = __halves2half2(h0, h1);
            *(__half2*)(outLo + (size_t)row * 512 + col)       = __halves2half2(l0, l1);
            *(__half2*)(outHi + (size_t)(row + 8) * 512 + col) = __halves2half2(h2, h3);
            *(__half2*)(outLo + (size_t)(row + 8) * 512 + col) = __halves2half2(l2, l3);
        }
    }
}

// ---------------- fp32 -> hi/lo fp16 (strided into concat buffer) ----------------
__global__ void __launch_bounds__(256)
conv_hilo(const float* __restrict__ src, int total4, int kshift, int kmask,
          int dstStride, int dstOff,
          __half* __restrict__ h, __half* __restrict__ l)
{
    int i = blockIdx.x * 256 + threadIdx.x;
    if (i >= total4) return;
    int e = i << 2;
    int row = e >> kshift, col = e & kmask;
    float4 v = *(const float4*)(src + e);
    size_t o = (size_t)row * dstStride + dstOff + col;
    __half h0, l0, h1, l1, h2, l2, h3, l3;
    hilo_split(v.x, h0, l0); hilo_split(v.y, h1, l1);
    hilo_split(v.z, h2, l2); hilo_split(v.w, h3, l3);
    __half2* hp = (__half2*)(h + o);
    __half2* lp = (__half2*)(l + o);
    hp[0] = __halves2half2(h0, h1); hp[1] = __halves2half2(h2, h3);
    lp[0] = __halves2half2(l0, l1); lp[1] = __halves2half2(l2, l3);
}

// ---------------- weight transpose + fp16: W[K,512] -> Wt[512,K] ----------------
__global__ void __launch_bounds__(256)
wt_conv(const float* __restrict__ W, int K, __half* __restrict__ T)
{
    __shared__ float t[32][33];
    const int nb = blockIdx.x * 32, kb = blockIdx.y * 32;
    const int tx = threadIdx.x & 31, ty = threadIdx.x >> 5;
#pragma unroll
    for (int i = 0; i < 32; i += 8)
        t[ty + i][tx] = W[(size_t)(kb + ty + i) * 512 + nb + tx];
    __syncthreads();
#pragma unroll
    for (int i = 0; i < 32; i += 8)
        T[(size_t)(nb + ty + i) * K + kb + tx] = __float2half_rn(t[tx][ty + i]);
}

// ---------------- weight composition ----------------
__global__ void __launch_bounds__(256)
compose_w(const float* __restrict__ A, const float* __restrict__ B, __half* __restrict__ T)
{
    __shared__ float As[64][17];
    __shared__ float Bs[16][68];
    const int i0 = blockIdx.y * 64, nb0 = blockIdx.x * 64;
    const int tx = threadIdx.x & 15, ty = threadIdx.x >> 4;
    float acc[4][4] = {};
    for (int j0 = 0; j0 < 512; j0 += 16) {
        for (int t = threadIdx.x; t < 1024; t += 256) {
            int r = t >> 4, jj = t & 15;
            As[r][jj] = A[(size_t)(i0 + r) * 512 + j0 + jj];
        }
        for (int t = threadIdx.x; t < 1024; t += 256) {
            int r = t >> 6, nn = t & 63;
            Bs[r][nn] = B[(size_t)(j0 + r) * 512 + nb0 + nn];
        }
        __syncthreads();
#pragma unroll
        for (int jj = 0; jj < 16; jj++) {
            float a[4], b[4];
#pragma unroll
            for (int u = 0; u < 4; u++) a[u] = As[ty * 4 + u][jj];
#pragma unroll
            for (int u = 0; u < 4; u++) b[u] = Bs[jj][tx * 4 + u];
#pragma unroll
            for (int u = 0; u < 4; u++)
#pragma unroll
                for (int v = 0; v < 4; v++) acc[u][v] += a[u] * b[v];
        }
        __syncthreads();
    }
#pragma unroll
    for (int u = 0; u < 4; u++)
#pragma unroll
        for (int v = 0; v < 4; v++) {
            int i = i0 + ty * 4 + u, n = nb0 + tx * 4 + v;
            T[(size_t)n * 512 + i] = __float2half_rn(acc[u][v]);
        }
}

// ---------------- composed qkv bias ----------------
__global__ void __launch_bounds__(512)
compose_bias(const float* __restrict__ b3,
             const float* __restrict__ Bq, const float* __restrict__ Bk, const float* __restrict__ Bv,
             const float* __restrict__ bq, const float* __restrict__ bk, const float* __restrict__ bv,
             float* __restrict__ bc)
{
    const int seg = blockIdx.x, n = threadIdx.x;
    const float* B = seg == 0 ? Bq : seg == 1 ? Bk : Bv;
    const float* bb = seg == 0 ? bq : seg == 1 ? bk : bv;
    float s = bb[n];
    for (int j = 0; j < 512; j++) s += b3[j] * B[(size_t)j * 512 + n];
    bc[seg * 512 + n] = s;
}

// ---------------- pack head biases: bh = bm | blv ----------------
__global__ void __launch_bounds__(512)
pack_hbias(const float* __restrict__ bm, const float* __restrict__ blv, float* __restrict__ bh)
{
    int t = threadIdx.x;
    bh[t] = bm[t]; bh[512 + t] = blv[t];
}

// ---------------- Attention: k staged, q in regs; writes seg as hi/lo fp16 ----------------
#define ATT_DSM (LMAX * 512 * 4)

__global__ void __launch_bounds__(256, 2)
attn_kernel(const float* __restrict__ qkv, const int* __restrict__ sse,
            __half* __restrict__ segh, __half* __restrict__ segl)
{
    extern __shared__ float ks[];
    __shared__ float scores[LMAX][LMAX];
    __shared__ float colsum[LMAX];

    const int b = blockIdx.x;
    const int tid = threadIdx.x;
    const int warp = tid >> 5, lane = tid & 31;
    const int start = sse[2 * b];
    const int len = sse[2 * b + 1] - start;

    const float4* g = (const float4*)(qkv + (size_t)start * 1536);

    {
        float4* k4 = (float4*)ks;
        int tot = len * 128;
        for (int i = tid; i < tot; i += 256) {
            int row = i >> 7, cc = i & 127;
            k4[i] = g[row * 384 + 128 + cc];
        }
    }
    __syncthreads();

    {
        const float scale = 0.044194173824159216f;
        const float4* k4 = (const float4*)ks;
        for (int l = warp; l < len; l += 8) {
            float4 q[4];
            const float4* qr = g + l * 384 + lane;
#pragma unroll
            for (int i = 0; i < 4; i++) q[i] = __ldg(qr + i * 32);
            for (int m = 0; m < len; m++) {
                const float4* kr = k4 + m * 128 + lane;
                float s = 0.f;
#pragma unroll
                for (int i = 0; i < 4; i++) {
                    float4 kv = kr[i * 32];
                    s += q[i].x * kv.x + q[i].y * kv.y + q[i].z * kv.z + q[i].w * kv.w;
                }
#pragma unroll
                for (int off = 16; off > 0; off >>= 1)
                    s += __shfl_xor_sync(0xffffffffu, s, off);
                if (lane == 0) scores[l][m] = s * scale;
            }
        }
    }
    __syncthreads();

    if (tid < len) {
        float mx = -1e30f;
        for (int m = 0; m < len; m++) mx = fmaxf(mx, scores[tid][m]);
        float sum = 0.f;
        for (int m = 0; m < len; m++) {
            float e = __expf(scores[tid][m] - mx);
            scores[tid][m] = e; sum += e;
        }
        float inv = 1.f / sum;
        for (int m = 0; m < len; m++) scores[tid][m] *= inv;
    }
    __syncthreads();

    if (tid < len) {
        float cs = 0.f;
        for (int l = 0; l < len; l++) cs += scores[l][tid];
        colsum[tid] = cs;
    }
    __syncthreads();

    const float invlen = 1.f / (float)len;
    for (int d = tid; d < 512; d += 256) {
        float s = 0.f;
        for (int m = 0; m < len; m++)
            s += colsum[m] * qkv[(size_t)(start + m) * 1536 + 1024 + d];
        float v = s * invlen;
        __half h, l;
        hilo_split(v, h, l);
        segh[(size_t)b * 512 + d] = h;
        segl[(size_t)b * 512 + d] = l;
    }
}

// ---------------- z: writes out_z + decoder concat z cols (both row blocks) ----------------
__global__ void __launch_bounds__(256)
z_kernel(const float* __restrict__ mean, const float* __restrict__ lv,
         const float* __restrict__ eps, float* __restrict__ zout,
         __half* __restrict__ dcath, __half* __restrict__ dcatl)
{
    __shared__ float red[256];
    const int b = blockIdx.x, tid = threadIdx.x;
    float zi[2];
    float ss = 0.f;
#pragma unroll
    for (int j = 0; j < 2; j++) {
        int d = tid + 256 * j;
        size_t idx = (size_t)b * 512 + d;
        float z = mean[idx] + __expf(0.5f * lv[idx]) * eps[idx];
        zi[j] = z; ss += z * z;
    }
    red[tid] = ss;
    __syncthreads();
    for (int s = 128; s > 0; s >>= 1) {
        if (tid < s) red[tid] += red[tid + s];
        __syncthreads();
    }
    float denom = fmaxf(sqrtf(red[0]), 1e-12f);
    float fac = 22.627416997969522f / denom;
#pragma unroll
    for (int j = 0; j < 2; j++) {
        int d = tid + 256 * j;
        float z = zi[j] * fac;
        zout[(size_t)b * 512 + d] = z;
        __half h, l;
        hilo_split(z, h, l);
        size_t o0 = (size_t)b * 1536 + 1024 + d;
        size_t o1 = o0 + (size_t)BATCH * 1536;
        dcath[o0] = h; dcatl[o0] = l;
        dcath[o1] = h; dcatl[o1] = l;
    }
}

// ---------------- final head matvec (4096 rows -> contiguous out) ----------------
__global__ void __launch_bounds__(256)
matvec_kernel(const float* __restrict__ A, const float* __restrict__ w,
              const float* __restrict__ b, float* __restrict__ out)
{
    const int lane = threadIdx.x;
    const int row = blockIdx.x * 8 + threadIdx.y;
    float s = 0.f;
    for (int k = lane; k < 512; k += 32)
        s += A[(size_t)row * 512 + k] * w[k];
#pragma unroll
    for (int off = 16; off > 0; off >>= 1)
        s += __shfl_xor_sync(0xffffffffu, s, off);
    if (lane == 0) out[row] = s + b[0];
}

// ---------------- host side ----------------
extern "C" void kernel_launch(void* const* d_in, const int* in_sizes, int n_in,
                              void* d_out, int out_size)
{
    const float* tc    = (const float*)d_in[0];
    const float* tr    = (const float*)d_in[1];
    const float* cc    = (const float*)d_in[2];
    const float* cr    = (const float*)d_in[3];
    const float* eps   = (const float*)d_in[4];
    const float* pe_w1 = (const float*)d_in[5];
    const float* pe_b1 = (const float*)d_in[6];
    const float* pe_w2 = (const float*)d_in[7];
    const float* pe_b2 = (const float*)d_in[8];
    const float* pe_w3 = (const float*)d_in[9];
    const float* pe_b3 = (const float*)d_in[10];
    const float* wq    = (const float*)d_in[11];
    const float* bq    = (const float*)d_in[12];
    const float* wk    = (const float*)d_in[13];
    const float* bk    = (const float*)d_in[14];
    const float* wv    = (const float*)d_in[15];
    const float* bv    = (const float*)d_in[16];
    const float* wm    = (const float*)d_in[17];
    const float* bm    = (const float*)d_in[18];
    const float* wlv   = (const float*)d_in[19];
    const float* blv   = (const float*)d_in[20];
    const float* d_w1  = (const float*)d_in[21];
    const float* d_b1  = (const float*)d_in[22];
    const float* d_w2  = (const float*)d_in[23];
    const float* d_b2  = (const float*)d_in[24];
    const float* d_w3  = (const float*)d_in[25];
    const float* d_b3  = (const float*)d_in[26];
    const int*   sse   = (const int*)d_in[27];

    float* out = (float*)d_out;
    float* out_rc   = out;                     // [2048] then rr contiguous at +2048
    float* out_mean = out + 2 * BATCH;
    float* out_lv   = out_mean + BATCH * 512;
    float* out_z    = out_lv + BATCH * 512;

    __half *a1h, *a1l, *a2h, *a2l;
    __half *dcath, *dcatl, *d1h, *d1l, *segh, *segl;
    __half *w1t, *w2t, *wct, *wht, *dw1t, *dw2t;
    float *qkvf, *d2f, *bc, *bh;
    cudaGetSymbolAddress((void**)&a1h, g_a1h);     cudaGetSymbolAddress((void**)&a1l, g_a1l);
    cudaGetSymbolAddress((void**)&a2h, g_a2h);     cudaGetSymbolAddress((void**)&a2l, g_a2l);
    cudaGetSymbolAddress((void**)&dcath, g_dcath); cudaGetSymbolAddress((void**)&dcatl, g_dcatl);
    cudaGetSymbolAddress((void**)&d1h, g_d1h);     cudaGetSymbolAddress((void**)&d1l, g_d1l);
    cudaGetSymbolAddress((void**)&segh, g_segh);   cudaGetSymbolAddress((void**)&segl, g_segl);
    cudaGetSymbolAddress((void**)&w1t, g_w1t);
    cudaGetSymbolAddress((void**)&w2t, g_w2t);
    cudaGetSymbolAddress((void**)&wct, g_wct);
    cudaGetSymbolAddress((void**)&wht, g_wht);
    cudaGetSymbolAddress((void**)&dw1t, g_dw1t);
    cudaGetSymbolAddress((void**)&dw2t, g_dw2t);
    cudaGetSymbolAddress((void**)&qkvf, g_qkv);
    cudaGetSymbolAddress((void**)&d2f, g_d2);
    cudaGetSymbolAddress((void**)&bc, g_bc);
    cudaGetSymbolAddress((void**)&bh, g_bh);

    cudaFuncSetAttribute(gemm_l1, cudaFuncAttributeMaxDynamicSharedMemorySize, L1_DSM);
    cudaFuncSetAttribute(gemm_mma<0, 1>, cudaFuncAttributeMaxDynamicSharedMemorySize, GEMM_DSM);
    cudaFuncSetAttribute(gemm_mma<1, 0>, cudaFuncAttributeMaxDynamicSharedMemorySize, GEMM_DSM);
    cudaFuncSetAttribute(gemm_mma<1, 1>, cudaFuncAttributeMaxDynamicSharedMemorySize, GEMM_DSM);
    cudaFuncSetAttribute(gemm_mma<2, 2>, cudaFuncAttributeMaxDynamicSharedMemorySize, GEMM_DSM);
    cudaFuncSetAttribute(attn_kernel, cudaFuncAttributeMaxDynamicSharedMemorySize, ATT_DSM);

    // layer 1 (fused input conversion)
    wt_conv<<<dim3(16, 64), 256>>>(pe_w1, 2048, w1t);
    gemm_l1<<<dim3(4, NCTX / 128), 256, L1_DSM>>>(cc, cr, w1t, pe_b1, a1h, a1l);

    wt_conv<<<dim3(16, 16), 256>>>(pe_w2, 512, w2t);
    gemm_mma<1, 0><<<dim3(4, NCTX / 128), 256, GEMM_DSM>>>(a1h, a1l, 512, w2t, pe_b2, 512, nullptr, a2h, a2l);

    // compose pe_w3 into qkv
    compose_w<<<dim3(8, 8), 256>>>(pe_w3, wq, wct);
    compose_w<<<dim3(8, 8), 256>>>(pe_w3, wk, wct + (size_t)512 * 512);
    compose_w<<<dim3(8, 8), 256>>>(pe_w3, wv, wct + (size_t)1024 * 512);
    compose_bias<<<3, 512>>>(pe_b3, wq, wk, wv, bq, bk, bv, bc);

    gemm_mma<0, 1><<<dim3(12, NCTX / 128), 256, GEMM_DSM>>>(a2h, a2l, 512, wct, bc, 1536, qkvf, nullptr, nullptr);

    // attention (writes seg hi/lo directly)
    attn_kernel<<<BATCH, 256, ATT_DSM>>>(qkvf, sse, segh, segl);

    // heads: packed N=1024 single GEMM, split-output epilogue
    wt_conv<<<dim3(16, 16), 256>>>(wm, 512, wht);
    wt_conv<<<dim3(16, 16), 256>>>(wlv, 512, wht + (size_t)512 * 512);
    pack_hbias<<<1, 512>>>(bm, blv, bh);
    gemm_mma<2, 2><<<dim3(8, BATCH / 128), 256, GEMM_DSM>>>(segh, segl, 512, wht, bh, 512, out_mean, nullptr, nullptr);

    // z (also fills decoder concat z columns for both row blocks)
    z_kernel<<<BATCH, 256>>>(out_mean, out_lv, eps, out_z, dcath, dcatl);

    // decoder weights
    wt_conv<<<dim3(16, 48), 256>>>(d_w1, 1536, dw1t);
    wt_conv<<<dim3(16, 16), 256>>>(d_w2, 512, dw2t);

    // decoder inputs: tc -> rows 0..2047, tr -> rows 2048..4095 (cols 0..1023)
    conv_hilo<<<BATCH * 1024 / 4 / 256, 256>>>(tc, BATCH * 1024 / 4, 10, 1023, 1536, 0, dcath, dcatl);
    conv_hilo<<<BATCH * 1024 / 4 / 256, 256>>>(tr, BATCH * 1024 / 4, 10, 1023, 1536, 0,
                                               dcath + (size_t)BATCH * 1536, dcatl + (size_t)BATCH * 1536);

    // batched decoder: M = 4096
    gemm_mma<1, 0><<<dim3(4, 2 * BATCH / 128), 256, GEMM_DSM>>>(dcath, dcatl, 1536, dw1t, d_b1, 512, nullptr, d1h, d1l);
    gemm_mma<1, 1><<<dim3(4, 2 * BATCH / 128), 256, GEMM_DSM>>>(d1h, d1l, 512, dw2t, d_b2, 512, d2f, nullptr, nullptr);
    matvec_kernel<<<2 * BATCH / 8, dim3(32, 8)>>>(d2f, d_w3, d_b3, out_rc);   // rc then rr contiguous

    (void)in_sizes; (void)n_in; (void)out_size;
}

// round 15
// speedup vs baseline: 2.6104x; 1.5018x over previous
#include <cuda_runtime.h>
#include <cuda_fp16.h>
#include <cstdint>

// ---------------- Problem constants ----------------
#define NCTX   65536
#define BATCH  2048
#define LMAX   48

// ---------------- low-level helpers ----------------
__device__ __forceinline__ uint32_t smem_u32(const void* p) {
    uint32_t a;
    asm("{ .reg .u64 t; cvta.to.shared.u64 t, %1; cvt.u32.u64 %0, t; }" : "=r"(a) : "l"(p));
    return a;
}
__device__ __forceinline__ void cp16(uint32_t s, const void* g) {
    asm volatile("cp.async.cg.shared.global [%0], [%1], 16;" :: "r"(s), "l"(g));
}
__device__ __forceinline__ void cp_commit() {
    asm volatile("cp.async.commit_group;" ::: "memory");
}
__device__ __forceinline__ void cp_wait1() {
    asm volatile("cp.async.wait_group 1;" ::: "memory");
}
__device__ __forceinline__ void cp_wait0() {
    asm volatile("cp.async.wait_group 0;" ::: "memory");
}
__device__ __forceinline__ void ldsm4(uint32_t& r0, uint32_t& r1, uint32_t& r2, uint32_t& r3,
                                      uint32_t addr) {
    asm volatile("ldmatrix.sync.aligned.m8n8.x4.shared.b16 {%0,%1,%2,%3}, [%4];"
                 : "=r"(r0), "=r"(r1), "=r"(r2), "=r"(r3) : "r"(addr));
}
__device__ __forceinline__ void mma16816(float* c, uint32_t a0, uint32_t a1, uint32_t a2,
                                         uint32_t a3, uint32_t b0, uint32_t b1) {
    asm volatile(
        "mma.sync.aligned.m16n8k16.row.col.f32.f16.f16.f32 "
        "{%0,%1,%2,%3}, {%4,%5,%6,%7}, {%8,%9}, {%0,%1,%2,%3};"
        : "+f"(c[0]), "+f"(c[1]), "+f"(c[2]), "+f"(c[3])
        : "r"(a0), "r"(a1), "r"(a2), "r"(a3), "r"(b0), "r"(b1));
}

// ---------------- Scratch (static device globals) ----------------
__device__ __half g_a1[NCTX * 512];
__device__ __half g_a2[NCTX * 512];
__device__ __half g_dcat[2 * BATCH * 1536];    // [4096, 1536]
__device__ __half g_d1[2 * BATCH * 512];
__device__ __half g_seg[BATCH * 512];
// transposed single-fp16 weights: Wt[n][k]
__device__ __half g_w1t[512 * 2048];
__device__ __half g_w2t[512 * 512];
__device__ __half g_wct[1536 * 512];      // composed pe_w3@Wqkv
__device__ __half g_wht[1024 * 512];      // packed wm | wlv
__device__ __half g_dw1t[512 * 1536];
__device__ __half g_dw2t[512 * 512];
__device__ float g_bc[1536];              // composed qkv bias
__device__ float g_bh[1024];              // packed bm | blv
// fp32 buffers
__device__ float g_qkv[NCTX * 1536];
__device__ float g_d2[2 * BATCH * 512];

// ---------------- generic HMMA GEMM (fp16 single-pass, 3-stage) ----------------
// OUTMODE: 0 = fp16 (ldc), 1 = fp32 (ldc), 2 = heads split fp32 (N=1024 -> two blocks)
#define STG_BYTES 20480u
#define GEMM_DSM  (3 * 20480)

template <int ACT, int OUTMODE>
__global__ void __launch_bounds__(256, 2)
gemm_mma(const __half* __restrict__ Ah, int K,
         const __half* __restrict__ Bt,
         const float* __restrict__ bias, int ldc,
         float* __restrict__ outF, __half* __restrict__ outH)
{
    extern __shared__ char dsm[];
    const uint32_t smBase = smem_u32(dsm);

    const int tid = threadIdx.x;
    const int lane = tid & 31;
    const int w = tid >> 5;
    const int warp_m = w >> 2;
    const int warp_n = w & 3;
    const int m0 = blockIdx.y * 128;
    const int n0 = blockIdx.x * 128;

    float c[4][4][4];
#pragma unroll
    for (int mi = 0; mi < 4; mi++)
#pragma unroll
        for (int ni = 0; ni < 4; ni++)
#pragma unroll
            for (int r = 0; r < 4; r++) c[mi][ni][r] = 0.f;

    const int nk = K >> 5;

    auto load_stage = [&](int s) {
        const uint32_t sb = smBase + (uint32_t)(s % 3) * STG_BYTES;
        const int k0 = s << 5;
#pragma unroll
        for (int j = 0; j < 2; j++) {
            int slot = tid + j * 256;
            int row = slot >> 2, k8 = slot & 3;
            uint32_t dst = sb + (uint32_t)row * 80u + (uint32_t)k8 * 16u;
            cp16(dst,           Ah + (size_t)(m0 + row) * K + k0 + k8 * 8);
            cp16(dst + 10240u,  Bt + (size_t)(n0 + row) * K + k0 + k8 * 8);
        }
    };

    load_stage(0); cp_commit();
    load_stage(1); cp_commit();

    const int lr = lane & 15;
    const uint32_t lc16 = (uint32_t)(lane >> 4) * 16u;

    for (int s = 0; s < nk; s++) {
        cp_wait1();
        __syncthreads();
        if (s + 2 < nk) load_stage(s + 2);
        cp_commit();

        const uint32_t sb = smBase + (uint32_t)(s % 3) * STG_BYTES;
#pragma unroll
        for (int h = 0; h < 2; h++) {
            const uint32_t koff = (uint32_t)h * 32u + lc16;
            uint32_t aa[4][4], bb[2][4];
#pragma unroll
            for (int mi = 0; mi < 4; mi++) {
                uint32_t addr = sb + (uint32_t)((warp_m * 64 + mi * 16 + lr) * 80) + koff;
                ldsm4(aa[mi][0], aa[mi][1], aa[mi][2], aa[mi][3], addr);
            }
#pragma unroll
            for (int bt = 0; bt < 2; bt++) {
                uint32_t addr = sb + 10240u + (uint32_t)((warp_n * 32 + bt * 16 + lr) * 80) + koff;
                ldsm4(bb[bt][0], bb[bt][1], bb[bt][2], bb[bt][3], addr);
            }
#pragma unroll
            for (int ni = 0; ni < 4; ni++) {
                const int bt = ni >> 1, sl = ni & 1;
#pragma unroll
                for (int mi = 0; mi < 4; mi++)
                    mma16816(c[mi][ni], aa[mi][0], aa[mi][1], aa[mi][2], aa[mi][3],
                             bb[bt][sl], bb[bt][sl + 2]);
            }
        }
    }

#pragma unroll
    for (int mi = 0; mi < 4; mi++) {
        const int row = m0 + warp_m * 64 + mi * 16 + (lane >> 2);
#pragma unroll
        for (int ni = 0; ni < 4; ni++) {
            const int col = n0 + warp_n * 32 + ni * 8 + (lane & 3) * 2;
            const float b0 = bias[col], b1 = bias[col + 1];
            float v0 = c[mi][ni][0] + b0, v1 = c[mi][ni][1] + b1;
            float v2 = c[mi][ni][2] + b0, v3 = c[mi][ni][3] + b1;
            if (ACT == 1) {
                v0 = v0 > 0.f ? v0 : 0.2f * v0;
                v1 = v1 > 0.f ? v1 : 0.2f * v1;
                v2 = v2 > 0.f ? v2 : 0.2f * v2;
                v3 = v3 > 0.f ? v3 : 0.2f * v3;
            } else if (ACT == 2) {
                v0 = fminf(fmaxf(v0, -1.f), 1.f);
                v1 = fminf(fmaxf(v1, -1.f), 1.f);
                v2 = fminf(fmaxf(v2, -1.f), 1.f);
                v3 = fminf(fmaxf(v3, -1.f), 1.f);
            }
            if (OUTMODE == 1) {
                *(float2*)(outF + (size_t)row * ldc + col)       = make_float2(v0, v1);
                *(float2*)(outF + (size_t)(row + 8) * ldc + col) = make_float2(v2, v3);
            } else if (OUTMODE == 2) {
                size_t base = (size_t)(col >> 9) * ((size_t)BATCH * 512) + (col & 511);
                *(float2*)(outF + base + (size_t)row * 512)       = make_float2(v0, v1);
                *(float2*)(outF + base + (size_t)(row + 8) * 512) = make_float2(v2, v3);
            } else {
                *(__half2*)(outH + (size_t)row * ldc + col) =
                    __halves2half2(__float2half_rn(v0), __float2half_rn(v1));
                *(__half2*)(outH + (size_t)(row + 8) * ldc + col) =
                    __halves2half2(__float2half_rn(v2), __float2half_rn(v3));
            }
        }
    }
}

// ---------------- layer-1 GEMM with fused fp32->fp16 conversion ----------------
// smem stage: [0,16384) A fp32 | [16384,26624) A fp16 | [26624,36864) B
#define L1_STG 36864u
#define L1_DSM (2 * 36864)

__global__ void __launch_bounds__(256, 2)
gemm_l1(const float* __restrict__ cc, const float* __restrict__ cr,
        const __half* __restrict__ Bt, const float* __restrict__ bias,
        __half* __restrict__ outH)
{
    extern __shared__ char dsm[];
    const uint32_t smBase = smem_u32(dsm);
    const int K = 2048, nk = 64;

    const int tid = threadIdx.x;
    const int lane = tid & 31;
    const int w = tid >> 5;
    const int warp_m = w >> 2;
    const int warp_n = w & 3;
    const int m0 = blockIdx.y * 128;
    const int n0 = blockIdx.x * 128;

    float c[4][4][4];
#pragma unroll
    for (int mi = 0; mi < 4; mi++)
#pragma unroll
        for (int ni = 0; ni < 4; ni++)
#pragma unroll
            for (int r = 0; r < 4; r++) c[mi][ni][r] = 0.f;

    auto load_stage = [&](int s) {
        const uint32_t sb = smBase + (uint32_t)(s & 1) * L1_STG;
        const int k0 = s << 5;
        const float* A = (k0 < 1024) ? cc : cr;
        const int kc = k0 & 1023;
#pragma unroll
        for (int j = 0; j < 4; j++) {
            int slot = tid + j * 256;
            int row = slot >> 3, c8 = slot & 7;
            cp16(sb + (uint32_t)row * 128u + (uint32_t)c8 * 16u,
                 A + (size_t)(m0 + row) * 1024 + kc + c8 * 4);
        }
#pragma unroll
        for (int j = 0; j < 2; j++) {
            int slot = tid + j * 256;
            int row = slot >> 2, k8 = slot & 3;
            cp16(sb + 26624u + (uint32_t)row * 80u + (uint32_t)k8 * 16u,
                 Bt + (size_t)(n0 + row) * 2048 + k0 + k8 * 8);
        }
    };

    load_stage(0); cp_commit();

    const int lr = lane & 15;
    const uint32_t lc16 = (uint32_t)(lane >> 4) * 16u;

    for (int s = 0; s < nk; s++) {
        cp_wait0();
        __syncthreads();
        if (s + 1 < nk) { load_stage(s + 1); cp_commit(); }

        const uint32_t sb = smBase + (uint32_t)(s & 1) * L1_STG;

        // convert A fp32 -> fp16 (80B-stride layout for ldsm)
#pragma unroll
        for (int j = 0; j < 4; j++) {
            int slot = tid + j * 256;
            int row = slot >> 3, c8 = slot & 7;
            float4 v = *(const float4*)(dsm + (size_t)((s & 1) * L1_STG) + row * 128 + c8 * 16);
            char* hp = dsm + (size_t)((s & 1) * L1_STG) + 16384 + row * 80 + c8 * 8;
            *(__half2*)(hp)     = __halves2half2(__float2half_rn(v.x), __float2half_rn(v.y));
            *(__half2*)(hp + 4) = __halves2half2(__float2half_rn(v.z), __float2half_rn(v.w));
        }
        __syncthreads();

#pragma unroll
        for (int h = 0; h < 2; h++) {
            const uint32_t koff = (uint32_t)h * 32u + lc16;
            uint32_t aa[4][4], bb[2][4];
#pragma unroll
            for (int mi = 0; mi < 4; mi++) {
                uint32_t addr = sb + 16384u + (uint32_t)((warp_m * 64 + mi * 16 + lr) * 80) + koff;
                ldsm4(aa[mi][0], aa[mi][1], aa[mi][2], aa[mi][3], addr);
            }
#pragma unroll
            for (int bt = 0; bt < 2; bt++) {
                uint32_t addr = sb + 26624u + (uint32_t)((warp_n * 32 + bt * 16 + lr) * 80) + koff;
                ldsm4(bb[bt][0], bb[bt][1], bb[bt][2], bb[bt][3], addr);
            }
#pragma unroll
            for (int ni = 0; ni < 4; ni++) {
                const int bt = ni >> 1, sl = ni & 1;
#pragma unroll
                for (int mi = 0; mi < 4; mi++)
                    mma16816(c[mi][ni], aa[mi][0], aa[mi][1], aa[mi][2], aa[mi][3],
                             bb[bt][sl], bb[bt][sl + 2]);
            }
        }
    }

#pragma unroll
    for (int mi = 0; mi < 4; mi++) {
        const int row = m0 + warp_m * 64 + mi * 16 + (lane >> 2);
#pragma unroll
        for (int ni = 0; ni < 4; ni++) {
            const int col = n0 + warp_n * 32 + ni * 8 + (lane & 3) * 2;
            const float b0 = bias[col], b1 = bias[col + 1];
            float v0 = c[mi][ni][0] + b0, v1 = c[mi][ni][1] + b1;
            float v2 = c[mi][ni][2] + b0, v3 = c[mi][ni][3] + b1;
            v0 = v0 > 0.f ? v0 : 0.2f * v0;
            v1 = v1 > 0.f ? v1 : 0.2f * v1;
            v2 = v2 > 0.f ? v2 : 0.2f * v2;
            v3 = v3 > 0.f ? v3 : 0.2f * v3;
            *(__half2*)(outH + (size_t)row * 512 + col) =
                __halves2half2(__float2half_rn(v0), __float2half_rn(v1));
            *(__half2*)(outH + (size_t)(row + 8) * 512 + col) =
                __halves2half2(__float2half_rn(v2), __float2half_rn(v3));
        }
    }
}

// ---------------- fp32 -> fp16 (strided into concat buffer) ----------------
__global__ void __launch_bounds__(256)
conv_h(const float* __restrict__ src, int total4, int kshift, int kmask,
       int dstStride, int dstOff, __half* __restrict__ h)
{
    int i = blockIdx.x * 256 + threadIdx.x;
    if (i >= total4) return;
    int e = i << 2;
    int row = e >> kshift, col = e & kmask;
    float4 v = *(const float4*)(src + e);
    size_t o = (size_t)row * dstStride + dstOff + col;
    __half2* hp = (__half2*)(h + o);
    hp[0] = __halves2half2(__float2half_rn(v.x), __float2half_rn(v.y));
    hp[1] = __halves2half2(__float2half_rn(v.z), __float2half_rn(v.w));
}

// ---------------- weight transpose + fp16: W[K,512] -> Wt[512,K] ----------------
__global__ void __launch_bounds__(256)
wt_conv(const float* __restrict__ W, int K, __half* __restrict__ T)
{
    __shared__ float t[32][33];
    const int nb = blockIdx.x * 32, kb = blockIdx.y * 32;
    const int tx = threadIdx.x & 31, ty = threadIdx.x >> 5;
#pragma unroll
    for (int i = 0; i < 32; i += 8)
        t[ty + i][tx] = W[(size_t)(kb + ty + i) * 512 + nb + tx];
    __syncthreads();
#pragma unroll
    for (int i = 0; i < 32; i += 8)
        T[(size_t)(nb + ty + i) * K + kb + tx] = __float2half_rn(t[tx][ty + i]);
}

// ---------------- weight composition ----------------
__global__ void __launch_bounds__(256)
compose_w(const float* __restrict__ A, const float* __restrict__ B, __half* __restrict__ T)
{
    __shared__ float As[64][17];
    __shared__ float Bs[16][68];
    const int i0 = blockIdx.y * 64, nb0 = blockIdx.x * 64;
    const int tx = threadIdx.x & 15, ty = threadIdx.x >> 4;
    float acc[4][4] = {};
    for (int j0 = 0; j0 < 512; j0 += 16) {
        for (int t = threadIdx.x; t < 1024; t += 256) {
            int r = t >> 4, jj = t & 15;
            As[r][jj] = A[(size_t)(i0 + r) * 512 + j0 + jj];
        }
        for (int t = threadIdx.x; t < 1024; t += 256) {
            int r = t >> 6, nn = t & 63;
            Bs[r][nn] = B[(size_t)(j0 + r) * 512 + nb0 + nn];
        }
        __syncthreads();
#pragma unroll
        for (int jj = 0; jj < 16; jj++) {
            float a[4], b[4];
#pragma unroll
            for (int u = 0; u < 4; u++) a[u] = As[ty * 4 + u][jj];
#pragma unroll
            for (int u = 0; u < 4; u++) b[u] = Bs[jj][tx * 4 + u];
#pragma unroll
            for (int u = 0; u < 4; u++)
#pragma unroll
                for (int v = 0; v < 4; v++) acc[u][v] += a[u] * b[v];
        }
        __syncthreads();
    }
#pragma unroll
    for (int u = 0; u < 4; u++)
#pragma unroll
        for (int v = 0; v < 4; v++) {
            int i = i0 + ty * 4 + u, n = nb0 + tx * 4 + v;
            T[(size_t)n * 512 + i] = __float2half_rn(acc[u][v]);
        }
}

// ---------------- composed qkv bias ----------------
__global__ void __launch_bounds__(512)
compose_bias(const float* __restrict__ b3,
             const float* __restrict__ Bq, const float* __restrict__ Bk, const float* __restrict__ Bv,
             const float* __restrict__ bq, const float* __restrict__ bk, const float* __restrict__ bv,
             float* __restrict__ bc)
{
    const int seg = blockIdx.x, n = threadIdx.x;
    const float* B = seg == 0 ? Bq : seg == 1 ? Bk : Bv;
    const float* bb = seg == 0 ? bq : seg == 1 ? bk : bv;
    float s = bb[n];
    for (int j = 0; j < 512; j++) s += b3[j] * B[(size_t)j * 512 + n];
    bc[seg * 512 + n] = s;
}

// ---------------- pack head biases ----------------
__global__ void __launch_bounds__(512)
pack_hbias(const float* __restrict__ bm, const float* __restrict__ blv, float* __restrict__ bh)
{
    int t = threadIdx.x;
    bh[t] = bm[t]; bh[512 + t] = blv[t];
}

// ---------------- Attention: k staged, q in regs; writes seg as fp16 ----------------
#define ATT_DSM (LMAX * 512 * 4)

__global__ void __launch_bounds__(256, 2)
attn_kernel(const float* __restrict__ qkv, const int* __restrict__ sse,
            __half* __restrict__ seg)
{
    extern __shared__ float ks[];
    __shared__ float scores[LMAX][LMAX];
    __shared__ float colsum[LMAX];

    const int b = blockIdx.x;
    const int tid = threadIdx.x;
    const int warp = tid >> 5, lane = tid & 31;
    const int start = sse[2 * b];
    const int len = sse[2 * b + 1] - start;

    const float4* g = (const float4*)(qkv + (size_t)start * 1536);

    {
        float4* k4 = (float4*)ks;
        int tot = len * 128;
        for (int i = tid; i < tot; i += 256) {
            int row = i >> 7, cc = i & 127;
            k4[i] = g[row * 384 + 128 + cc];
        }
    }
    __syncthreads();

    {
        const float scale = 0.044194173824159216f;
        const float4* k4 = (const float4*)ks;
        for (int l = warp; l < len; l += 8) {
            float4 q[4];
            const float4* qr = g + l * 384 + lane;
#pragma unroll
            for (int i = 0; i < 4; i++) q[i] = __ldg(qr + i * 32);
            for (int m = 0; m < len; m++) {
                const float4* kr = k4 + m * 128 + lane;
                float s = 0.f;
#pragma unroll
                for (int i = 0; i < 4; i++) {
                    float4 kv = kr[i * 32];
                    s += q[i].x * kv.x + q[i].y * kv.y + q[i].z * kv.z + q[i].w * kv.w;
                }
#pragma unroll
                for (int off = 16; off > 0; off >>= 1)
                    s += __shfl_xor_sync(0xffffffffu, s, off);
                if (lane == 0) scores[l][m] = s * scale;
            }
        }
    }
    __syncthreads();

    if (tid < len) {
        float mx = -1e30f;
        for (int m = 0; m < len; m++) mx = fmaxf(mx, scores[tid][m]);
        float sum = 0.f;
        for (int m = 0; m < len; m++) {
            float e = __expf(scores[tid][m] - mx);
            scores[tid][m] = e; sum += e;
        }
        float inv = 1.f / sum;
        for (int m = 0; m < len; m++) scores[tid][m] *= inv;
    }
    __syncthreads();

    if (tid < len) {
        float cs = 0.f;
        for (int l = 0; l < len; l++) cs += scores[l][tid];
        colsum[tid] = cs;
    }
    __syncthreads();

    const float invlen = 1.f / (float)len;
    for (int d = tid; d < 512; d += 256) {
        float s = 0.f;
        for (int m = 0; m < len; m++)
            s += colsum[m] * qkv[(size_t)(start + m) * 1536 + 1024 + d];
        seg[(size_t)b * 512 + d] = __float2half_rn(s * invlen);
    }
}

// ---------------- z: writes out_z + decoder concat z cols (both row blocks) ----------------
__global__ void __launch_bounds__(256)
z_kernel(const float* __restrict__ mean, const float* __restrict__ lv,
         const float* __restrict__ eps, float* __restrict__ zout,
         __half* __restrict__ dcat)
{
    __shared__ float red[256];
    const int b = blockIdx.x, tid = threadIdx.x;
    float zi[2];
    float ss = 0.f;
#pragma unroll
    for (int j = 0; j < 2; j++) {
        int d = tid + 256 * j;
        size_t idx = (size_t)b * 512 + d;
        float z = mean[idx] + __expf(0.5f * lv[idx]) * eps[idx];
        zi[j] = z; ss += z * z;
    }
    red[tid] = ss;
    __syncthreads();
    for (int s = 128; s > 0; s >>= 1) {
        if (tid < s) red[tid] += red[tid + s];
        __syncthreads();
    }
    float denom = fmaxf(sqrtf(red[0]), 1e-12f);
    float fac = 22.627416997969522f / denom;
#pragma unroll
    for (int j = 0; j < 2; j++) {
        int d = tid + 256 * j;
        float z = zi[j] * fac;
        zout[(size_t)b * 512 + d] = z;
        __half h = __float2half_rn(z);
        size_t o0 = (size_t)b * 1536 + 1024 + d;
        dcat[o0] = h;
        dcat[o0 + (size_t)BATCH * 1536] = h;
    }
}

// ---------------- final head matvec (4096 rows -> contiguous out) ----------------
__global__ void __launch_bounds__(256)
matvec_kernel(const float* __restrict__ A, const float* __restrict__ w,
              const float* __restrict__ b, float* __restrict__ out)
{
    const int lane = threadIdx.x;
    const int row = blockIdx.x * 8 + threadIdx.y;
    float s = 0.f;
    for (int k = lane; k < 512; k += 32)
        s += A[(size_t)row * 512 + k] * w[k];
#pragma unroll
    for (int off = 16; off > 0; off >>= 1)
        s += __shfl_xor_sync(0xffffffffu, s, off);
    if (lane == 0) out[row] = s + b[0];
}

// ---------------- host side ----------------
extern "C" void kernel_launch(void* const* d_in, const int* in_sizes, int n_in,
                              void* d_out, int out_size)
{
    const float* tc    = (const float*)d_in[0];
    const float* tr    = (const float*)d_in[1];
    const float* cc    = (const float*)d_in[2];
    const float* cr    = (const float*)d_in[3];
    const float* eps   = (const float*)d_in[4];
    const float* pe_w1 = (const float*)d_in[5];
    const float* pe_b1 = (const float*)d_in[6];
    const float* pe_w2 = (const float*)d_in[7];
    const float* pe_b2 = (const float*)d_in[8];
    const float* pe_w3 = (const float*)d_in[9];
    const float* pe_b3 = (const float*)d_in[10];
    const float* wq    = (const float*)d_in[11];
    const float* bq    = (const float*)d_in[12];
    const float* wk    = (const float*)d_in[13];
    const float* bk    = (const float*)d_in[14];
    const float* wv    = (const float*)d_in[15];
    const float* bv    = (const float*)d_in[16];
    const float* wm    = (const float*)d_in[17];
    const float* bm    = (const float*)d_in[18];
    const float* wlv   = (const float*)d_in[19];
    const float* blv   = (const float*)d_in[20];
    const float* d_w1  = (const float*)d_in[21];
    const float* d_b1  = (const float*)d_in[22];
    const float* d_w2  = (const float*)d_in[23];
    const float* d_b2  = (const float*)d_in[24];
    const float* d_w3  = (const float*)d_in[25];
    const float* d_b3  = (const float*)d_in[26];
    const int*   sse   = (const int*)d_in[27];

    float* out = (float*)d_out;
    float* out_rc   = out;                     // [2048] then rr contiguous at +2048
    float* out_mean = out + 2 * BATCH;
    float* out_lv   = out_mean + BATCH * 512;
    float* out_z    = out_lv + BATCH * 512;

    __half *a1, *a2, *dcat, *d1, *seg;
    __half *w1t, *w2t, *wct, *wht, *dw1t, *dw2t;
    float *qkvf, *d2f, *bc, *bh;
    cudaGetSymbolAddress((void**)&a1, g_a1);
    cudaGetSymbolAddress((void**)&a2, g_a2);
    cudaGetSymbolAddress((void**)&dcat, g_dcat);
    cudaGetSymbolAddress((void**)&d1, g_d1);
    cudaGetSymbolAddress((void**)&seg, g_seg);
    cudaGetSymbolAddress((void**)&w1t, g_w1t);
    cudaGetSymbolAddress((void**)&w2t, g_w2t);
    cudaGetSymbolAddress((void**)&wct, g_wct);
    cudaGetSymbolAddress((void**)&wht, g_wht);
    cudaGetSymbolAddress((void**)&dw1t, g_dw1t);
    cudaGetSymbolAddress((void**)&dw2t, g_dw2t);
    cudaGetSymbolAddress((void**)&qkvf, g_qkv);
    cudaGetSymbolAddress((void**)&d2f, g_d2);
    cudaGetSymbolAddress((void**)&bc, g_bc);
    cudaGetSymbolAddress((void**)&bh, g_bh);

    cudaFuncSetAttribute(gemm_l1, cudaFuncAttributeMaxDynamicSharedMemorySize, L1_DSM);
    cudaFuncSetAttribute(gemm_mma<0, 1>, cudaFuncAttributeMaxDynamicSharedMemorySize, GEMM_DSM);
    cudaFuncSetAttribute(gemm_mma<1, 0>, cudaFuncAttributeMaxDynamicSharedMemorySize, GEMM_DSM);
    cudaFuncSetAttribute(gemm_mma<1, 1>, cudaFuncAttributeMaxDynamicSharedMemorySize, GEMM_DSM);
    cudaFuncSetAttribute(gemm_mma<2, 2>, cudaFuncAttributeMaxDynamicSharedMemorySize, GEMM_DSM);
    cudaFuncSetAttribute(attn_kernel, cudaFuncAttributeMaxDynamicSharedMemorySize, ATT_DSM);

    // layer 1 (fused input conversion)
    wt_conv<<<dim3(16, 64), 256>>>(pe_w1, 2048, w1t);
    gemm_l1<<<dim3(4, NCTX / 128), 256, L1_DSM>>>(cc, cr, w1t, pe_b1, a1);

    wt_conv<<<dim3(16, 16), 256>>>(pe_w2, 512, w2t);
    gemm_mma<1, 0><<<dim3(4, NCTX / 128), 256, GEMM_DSM>>>(a1, 512, w2t, pe_b2, 512, nullptr, a2);

    // compose pe_w3 into qkv
    compose_w<<<dim3(8, 8), 256>>>(pe_w3, wq, wct);
    compose_w<<<dim3(8, 8), 256>>>(pe_w3, wk, wct + (size_t)512 * 512);
    compose_w<<<dim3(8, 8), 256>>>(pe_w3, wv, wct + (size_t)1024 * 512);
    compose_bias<<<3, 512>>>(pe_b3, wq, wk, wv, bq, bk, bv, bc);

    gemm_mma<0, 1><<<dim3(12, NCTX / 128), 256, GEMM_DSM>>>(a2, 512, wct, bc, 1536, qkvf, nullptr);

    // attention (writes seg fp16 directly)
    attn_kernel<<<BATCH, 256, ATT_DSM>>>(qkvf, sse, seg);

    // heads: packed N=1024 single GEMM, split-output epilogue
    wt_conv<<<dim3(16, 16), 256>>>(wm, 512, wht);
    wt_conv<<<dim3(16, 16), 256>>>(wlv, 512, wht + (size_t)512 * 512);
    pack_hbias<<<1, 512>>>(bm, blv, bh);
    gemm_mma<2, 2><<<dim3(8, BATCH / 128), 256, GEMM_DSM>>>(seg, 512, wht, bh, 512, out_mean, nullptr);

    // z (also fills decoder concat z columns for both row blocks)
    z_kernel<<<BATCH, 256>>>(out_mean, out_lv, eps, out_z, dcat);

    // decoder weights
    wt_conv<<<dim3(16, 48), 256>>>(d_w1, 1536, dw1t);
    wt_conv<<<dim3(16, 16), 256>>>(d_w2, 512, dw2t);

    // decoder inputs: tc -> rows 0..2047, tr -> rows 2048..4095 (cols 0..1023)
    conv_h<<<BATCH * 1024 / 4 / 256, 256>>>(tc, BATCH * 1024 / 4, 10, 1023, 1536, 0, dcat);
    conv_h<<<BATCH * 1024 / 4 / 256, 256>>>(tr, BATCH * 1024 / 4, 10, 1023, 1536, 0,
                                            dcat + (size_t)BATCH * 1536);

    // batched decoder: M = 4096
    gemm_mma<1, 0><<<dim3(4, 2 * BATCH / 128), 256, GEMM_DSM>>>(dcat, 1536, dw1t, d_b1, 512, nullptr, d1);
    gemm_mma<1, 1><<<dim3(4, 2 * BATCH / 128), 256, GEMM_DSM>>>(d1, 512, dw2t, d_b2, 512, d2f, nullptr);
    matvec_kernel<<<2 * BATCH / 8, dim3(32, 8)>>>(d2f, d_w3, d_b3, out_rc);

    (void)in_sizes; (void)n_in; (void)out_size;
}